// round 1
// baseline (speedup 1.0000x reference)
#include <cuda_runtime.h>
#include <math.h>

// ---------------- problem constants ----------------
#define BATCH   32
#define HH      56
#define WIMG    56
#define DIM     256
#define HEADS   8
#define HD      32          // head dim
#define WS      7
#define SHIFT   3
#define NTOK    49          // tokens per window
#define NWIN    64          // windows per image
#define HIDDEN  1024
#define T_TOK   100352      // BATCH * HH * WIMG

// ---------------- scratch (static device, no allocations) ----------------
__device__ float g_bufA[(size_t)T_TOK * 1024];   // qkv [T,768] then fc1-out [T,1024]
__device__ float g_bufB[(size_t)T_TOK * 256];    // hwin / attn_out / h2 (phase-reused)
__device__ float g_bufX[(size_t)T_TOK * 256];    // x after first residual (pixel order)

// map window-order token -> pixel-order token (applies un-shift; same map both ways)
__device__ __forceinline__ int win_to_pix(int m) {
    int n_in = m % NTOK;
    int wv   = m / NTOK;
    int bimg = wv >> 6;          // / NWIN
    int wi   = wv & 63;
    int wh   = wi >> 3;          // / (WIMG/WS)
    int wc   = wi & 7;
    int i    = n_in / WS;
    int j    = n_in - i * WS;
    int pr   = wh * WS + i + SHIFT; if (pr >= HH)   pr -= HH;
    int pc   = wc * WS + j + SHIFT; if (pc >= WIMG) pc -= WIMG;
    return bimg * (HH * WIMG) + pr * WIMG + pc;
}

// ---------------- LayerNorm (1 warp / token), optional shift+window gather ----
template<int DO_SHIFT>
__global__ __launch_bounds__(256) void ln_kernel(
    const float* __restrict__ x, const float* __restrict__ w,
    const float* __restrict__ b, float* __restrict__ out)
{
    int t    = blockIdx.x * 8 + (threadIdx.x >> 5);   // token in OUTPUT order
    int lane = threadIdx.x & 31;
    int src  = DO_SHIFT ? win_to_pix(t) : t;          // gather source (pixel order)

    const float4* px = (const float4*)(x + (size_t)src * DIM) + lane * 2;
    float4 v0 = px[0], v1 = px[1];

    float s  = v0.x + v0.y + v0.z + v0.w + v1.x + v1.y + v1.z + v1.w;
    float ss = v0.x*v0.x + v0.y*v0.y + v0.z*v0.z + v0.w*v0.w
             + v1.x*v1.x + v1.y*v1.y + v1.z*v1.z + v1.w*v1.w;
    #pragma unroll
    for (int o = 16; o; o >>= 1) {
        s  += __shfl_xor_sync(0xffffffffu, s,  o);
        ss += __shfl_xor_sync(0xffffffffu, ss, o);
    }
    float mean = s * (1.0f / DIM);
    float var  = ss * (1.0f / DIM) - mean * mean;
    float rstd = rsqrtf(var + 1e-5f);

    int c0 = lane * 8;
    const float4* pw = (const float4*)(w + c0);
    const float4* pb = (const float4*)(b + c0);
    float4 w0 = pw[0], w1 = pw[1], b0 = pb[0], b1 = pb[1];
    float4 o0, o1;
    o0.x = (v0.x - mean) * rstd * w0.x + b0.x;
    o0.y = (v0.y - mean) * rstd * w0.y + b0.y;
    o0.z = (v0.z - mean) * rstd * w0.z + b0.z;
    o0.w = (v0.w - mean) * rstd * w0.w + b0.w;
    o1.x = (v1.x - mean) * rstd * w1.x + b1.x;
    o1.y = (v1.y - mean) * rstd * w1.y + b1.y;
    o1.z = (v1.z - mean) * rstd * w1.z + b1.z;
    o1.w = (v1.w - mean) * rstd * w1.w + b1.w;
    float4* po = (float4*)(out + (size_t)t * DIM) + lane * 2;
    po[0] = o0; po[1] = o1;
}

// ---------------- SGEMM: C = A[M,K] @ Bw[N,K]^T + bias, with epilogues ------
// EPI: 0 = none, 1 = exact GELU, 2 = + res[m], 3 = scatter to win_to_pix(m) and + res
#define BM 128
#define BN 128
#define BK 8
#define TM 8
#define TN 8

template<int EPI>
__global__ __launch_bounds__(256) void gemm_kernel(
    const float* __restrict__ A, const float* __restrict__ Bw,
    const float* __restrict__ bias, const float* __restrict__ res,
    float* __restrict__ C, int M, int Nout, int K)
{
    __shared__ float As[BK][BM];
    __shared__ float Bs[BK][BN];

    int tid = threadIdx.x;
    int m0  = blockIdx.y * BM;
    int n0  = blockIdx.x * BN;

    int loadRow = tid >> 1;            // 0..127
    int loadCol = (tid & 1) * 4;       // 0 or 4

    int tx = tid & 15, ty = tid >> 4;  // 16x16 thread grid, 8x8 per thread
    float acc[TM][TN] = {};

    const float* Ag = A  + (size_t)(m0 + loadRow) * K + loadCol;
    const float* Bg = Bw + (size_t)(n0 + loadRow) * K + loadCol;

    for (int k0 = 0; k0 < K; k0 += BK) {
        float4 a4 = *(const float4*)(Ag + k0);
        float4 b4 = *(const float4*)(Bg + k0);
        As[loadCol + 0][loadRow] = a4.x;
        As[loadCol + 1][loadRow] = a4.y;
        As[loadCol + 2][loadRow] = a4.z;
        As[loadCol + 3][loadRow] = a4.w;
        Bs[loadCol + 0][loadRow] = b4.x;
        Bs[loadCol + 1][loadRow] = b4.y;
        Bs[loadCol + 2][loadRow] = b4.z;
        Bs[loadCol + 3][loadRow] = b4.w;
        __syncthreads();

        #pragma unroll
        for (int k = 0; k < BK; ++k) {
            float ra[TM], rb[TN];
            #pragma unroll
            for (int i = 0; i < TM; ++i) ra[i] = As[k][ty * TM + i];
            #pragma unroll
            for (int j = 0; j < TN; ++j) rb[j] = Bs[k][tx * TN + j];
            #pragma unroll
            for (int i = 0; i < TM; ++i)
                #pragma unroll
                for (int j = 0; j < TN; ++j)
                    acc[i][j] += ra[i] * rb[j];
        }
        __syncthreads();
    }

    const float kSqrt1_2 = 0.70710678118654752440f;
    float bi[TN];
    #pragma unroll
    for (int j = 0; j < TN; ++j) bi[j] = bias[n0 + tx * TN + j];

    #pragma unroll
    for (int i = 0; i < TM; ++i) {
        int m = m0 + ty * TM + i;
        int dm = (EPI == 3) ? win_to_pix(m) : m;
        float*       crow = C + (size_t)dm * Nout + n0 + tx * TN;
        const float* rrow = (EPI == 2 || EPI == 3)
                          ? res + (size_t)dm * Nout + n0 + tx * TN : nullptr;
        #pragma unroll
        for (int j = 0; j < TN; ++j) {
            float v = acc[i][j] + bi[j];
            if (EPI == 1) v = 0.5f * v * (1.0f + erff(v * kSqrt1_2));
            if (EPI == 2 || EPI == 3) v += rrow[j];
            crow[j] = v;
        }
    }
}

// ---------------- windowed attention: one CTA per (window, head) ------------
__global__ __launch_bounds__(256) void attn_kernel(
    const float* __restrict__ qkv, const float* __restrict__ rpb,
    const int* __restrict__ rel_idx, const float* __restrict__ mask,
    float* __restrict__ out)
{
    __shared__ float sq[NTOK][HD];
    __shared__ float sk[NTOK][HD];
    __shared__ float sv[NTOK][HD];
    __shared__ float S[NTOK][NTOK];

    int blk = blockIdx.x;
    int h   = blk & (HEADS - 1);
    int wv  = blk >> 3;            // global window index
    int wi  = wv & (NWIN - 1);     // window within image (for mask)
    int tid = threadIdx.x;
    const float scale = 0.17677669529663688f;   // 32^-0.5

    for (int idx = tid; idx < NTOK * HD; idx += 256) {
        int n = idx >> 5, d = idx & 31;
        size_t base = (size_t)(wv * NTOK + n) * 768 + h * HD + d;
        sq[n][d] = qkv[base] * scale;
        sk[n][d] = qkv[base + 256];
        sv[n][d] = qkv[base + 512];
    }
    __syncthreads();

    for (int idx = tid; idx < NTOK * NTOK; idx += 256) {
        int n = idx / NTOK, m = idx - n * NTOK;
        float a = 0.0f;
        #pragma unroll
        for (int d = 0; d < HD; ++d) a += sq[n][d] * sk[m][d];
        a += rpb[rel_idx[idx] * HEADS + h];
        a += mask[(size_t)wi * (NTOK * NTOK) + idx];
        S[n][m] = a;
    }
    __syncthreads();

    int warp = tid >> 5, lane = tid & 31;
    for (int r = warp; r < NTOK; r += 8) {
        float mx = -1e30f;
        for (int m = lane; m < NTOK; m += 32) mx = fmaxf(mx, S[r][m]);
        #pragma unroll
        for (int o = 16; o; o >>= 1) mx = fmaxf(mx, __shfl_xor_sync(0xffffffffu, mx, o));
        float sum = 0.0f;
        for (int m = lane; m < NTOK; m += 32) {
            float e = __expf(S[r][m] - mx);
            S[r][m] = e;
            sum += e;
        }
        #pragma unroll
        for (int o = 16; o; o >>= 1) sum += __shfl_xor_sync(0xffffffffu, sum, o);
        float inv = 1.0f / sum;
        for (int m = lane; m < NTOK; m += 32) S[r][m] *= inv;
    }
    __syncthreads();

    for (int idx = tid; idx < NTOK * HD; idx += 256) {
        int n = idx >> 5, d = idx & 31;
        float a = 0.0f;
        #pragma unroll
        for (int m = 0; m < NTOK; ++m) a += S[n][m] * sv[m][d];
        out[(size_t)(wv * NTOK + n) * DIM + h * HD + d] = a;
    }
}

// ---------------- launch --------------------------------------------------
extern "C" void kernel_launch(void* const* d_in, const int* in_sizes, int n_in,
                              void* d_out, int out_size) {
    const float* x     = (const float*)d_in[0];
    const float* n1w   = (const float*)d_in[1];
    const float* n1b   = (const float*)d_in[2];
    const float* qkvw  = (const float*)d_in[3];
    const float* qkvb  = (const float*)d_in[4];
    const float* rpb   = (const float*)d_in[5];
    const float* projw = (const float*)d_in[6];
    const float* projb = (const float*)d_in[7];
    const float* n2w   = (const float*)d_in[8];
    const float* n2b   = (const float*)d_in[9];
    const float* fc1w  = (const float*)d_in[10];
    const float* fc1b  = (const float*)d_in[11];
    const float* fc2w  = (const float*)d_in[12];
    const float* fc2b  = (const float*)d_in[13];
    const int*   relix = (const int*)d_in[14];
    const float* mask  = (const float*)d_in[15];
    float* out = (float*)d_out;

    float *bufA, *bufB, *bufX;
    cudaGetSymbolAddress((void**)&bufA, g_bufA);
    cudaGetSymbolAddress((void**)&bufB, g_bufB);
    cudaGetSymbolAddress((void**)&bufX, g_bufX);

    const int LN_BLOCKS = T_TOK / 8;       // 12544
    const int MT = T_TOK / BM;             // 784

    // 1) LN1 + cyclic shift + window partition  (x -> bufB, window order)
    ln_kernel<1><<<LN_BLOCKS, 256>>>(x, n1w, n1b, bufB);

    // 2) qkv = hwin @ qkv_w^T + b   -> bufA [T,768]
    gemm_kernel<0><<<dim3(768 / BN, MT), 256>>>(bufB, qkvw, qkvb, nullptr, bufA,
                                                T_TOK, 768, DIM);

    // 3) windowed attention -> bufB [T,256] (window order)
    attn_kernel<<<(T_TOK / NTOK) * HEADS, 256>>>(bufA, rpb, relix, mask, bufB);

    // 4) proj + window-reverse + un-shift + residual -> bufX (pixel order)
    gemm_kernel<3><<<dim3(DIM / BN, MT), 256>>>(bufB, projw, projb, x, bufX,
                                                T_TOK, DIM, DIM);

    // 5) LN2 (bufX -> bufB, token order)
    ln_kernel<0><<<LN_BLOCKS, 256>>>(bufX, n2w, n2b, bufB);

    // 6) fc1 + exact GELU -> bufA [T,1024]
    gemm_kernel<1><<<dim3(HIDDEN / BN, MT), 256>>>(bufB, fc1w, fc1b, nullptr, bufA,
                                                   T_TOK, HIDDEN, DIM);

    // 7) fc2 + residual -> d_out
    gemm_kernel<2><<<dim3(DIM / BN, MT), 256>>>(bufA, fc2w, fc2b, bufX, out,
                                                T_TOK, DIM, HIDDEN);
}

// round 3
// speedup vs baseline: 1.1444x; 1.1444x over previous
#include <cuda_runtime.h>
#include <cstdint>
#include <math.h>

// ---------------- problem constants ----------------
#define BATCH   32
#define HH      56
#define WIMG    56
#define DIM     256
#define HEADS   8
#define HD      32          // head dim
#define WS      7
#define SHIFT   3
#define NTOK    49          // tokens per window
#define NWIN    64          // windows per image
#define HIDDEN  1024
#define T_TOK   100352      // BATCH * HH * WIMG

// ---------------- scratch (static device, no allocations) ----------------
__device__ float g_bufA[(size_t)T_TOK * 1024];   // qkv [T,768] then fc1-out [T,1024]
__device__ float g_bufB[(size_t)T_TOK * 256];    // hwin / attn_out / h2 (phase-reused)
__device__ float g_bufX[(size_t)T_TOK * 256];    // x after first residual (pixel order)

// ---------------- helpers ----------------
__device__ __forceinline__ uint32_t smem_u32(const void* p) {
    uint32_t a;
    asm("{ .reg .u64 t; cvta.to.shared.u64 t, %1; cvt.u32.u64 %0, t; }" : "=r"(a) : "l"(p));
    return a;
}

#define CP_ASYNC16(dst, src) \
    asm volatile("cp.async.cg.shared.global [%0], [%1], 16;\n" :: "r"(dst), "l"(src))
#define CP_COMMIT() asm volatile("cp.async.commit_group;\n" ::: "memory")
#define CP_WAIT2()  asm volatile("cp.async.wait_group 2;\n" ::: "memory")

__device__ __forceinline__ uint32_t f2tf(float x) {
    uint32_t r;
    asm("cvt.rna.tf32.f32 %0, %1;" : "=r"(r) : "f"(x));
    return r;
}

// D[16x8] += A[16x8] * B[8x8]; tf32 inputs, f32 accumulate
__device__ __forceinline__ void mma_tf32(float* d, const uint32_t* a, const uint32_t* b) {
    asm volatile(
        "mma.sync.aligned.m16n8k8.row.col.f32.tf32.tf32.f32 "
        "{%0,%1,%2,%3}, {%4,%5,%6,%7}, {%8,%9}, {%0,%1,%2,%3};"
        : "+f"(d[0]), "+f"(d[1]), "+f"(d[2]), "+f"(d[3])
        : "r"(a[0]), "r"(a[1]), "r"(a[2]), "r"(a[3]), "r"(b[0]), "r"(b[1]));
}

// map window-order token -> pixel-order token (applies un-shift)
__device__ __forceinline__ int win_to_pix(int m) {
    int n_in = m % NTOK;
    int wv   = m / NTOK;
    int bimg = wv >> 6;
    int wi   = wv & 63;
    int wh   = wi >> 3;
    int wc   = wi & 7;
    int i    = n_in / WS;
    int j    = n_in - i * WS;
    int pr   = wh * WS + i + SHIFT; if (pr >= HH)   pr -= HH;
    int pc   = wc * WS + j + SHIFT; if (pc >= WIMG) pc -= WIMG;
    return bimg * (HH * WIMG) + pr * WIMG + pc;
}

// ---------------- LayerNorm (1 warp / token), optional shift+window gather ----
template<int DO_SHIFT>
__global__ __launch_bounds__(256) void ln_kernel(
    const float* __restrict__ x, const float* __restrict__ w,
    const float* __restrict__ b, float* __restrict__ out)
{
    int t    = blockIdx.x * 8 + (threadIdx.x >> 5);
    int lane = threadIdx.x & 31;
    int src  = DO_SHIFT ? win_to_pix(t) : t;

    const float4* px = (const float4*)(x + (size_t)src * DIM) + lane * 2;
    float4 v0 = px[0], v1 = px[1];

    float s  = v0.x + v0.y + v0.z + v0.w + v1.x + v1.y + v1.z + v1.w;
    float ss = v0.x*v0.x + v0.y*v0.y + v0.z*v0.z + v0.w*v0.w
             + v1.x*v1.x + v1.y*v1.y + v1.z*v1.z + v1.w*v1.w;
    #pragma unroll
    for (int o = 16; o; o >>= 1) {
        s  += __shfl_xor_sync(0xffffffffu, s,  o);
        ss += __shfl_xor_sync(0xffffffffu, ss, o);
    }
    float mean = s * (1.0f / DIM);
    float var  = ss * (1.0f / DIM) - mean * mean;
    float rstd = rsqrtf(var + 1e-5f);

    int c0 = lane * 8;
    const float4* pw = (const float4*)(w + c0);
    const float4* pb = (const float4*)(b + c0);
    float4 w0 = pw[0], w1 = pw[1], b0 = pb[0], b1 = pb[1];
    float4 o0, o1;
    o0.x = (v0.x - mean) * rstd * w0.x + b0.x;
    o0.y = (v0.y - mean) * rstd * w0.y + b0.y;
    o0.z = (v0.z - mean) * rstd * w0.z + b0.z;
    o0.w = (v0.w - mean) * rstd * w0.w + b0.w;
    o1.x = (v1.x - mean) * rstd * w1.x + b1.x;
    o1.y = (v1.y - mean) * rstd * w1.y + b1.y;
    o1.z = (v1.z - mean) * rstd * w1.z + b1.z;
    o1.w = (v1.w - mean) * rstd * w1.w + b1.w;
    float4* po = (float4*)(out + (size_t)t * DIM) + lane * 2;
    po[0] = o0; po[1] = o1;
}

// ---------------- tf32 mma.sync GEMM: C = A[M,K] @ Bw[N,K]^T + bias ---------
// CTA tile 128x256, warp tile 64x64 (8 warps, 2x4), BK=32, 3-stage cp.async.
// EPI: 0 = none, 1 = exact GELU, 2 = + res[m], 3 = scatter win_to_pix(m) + res
#define LDT 36
#define A_ELEMS (128 * LDT)
#define B_ELEMS (256 * LDT)
#define STAGE_ELEMS (A_ELEMS + B_ELEMS)

template<int EPI>
__global__ __launch_bounds__(256) void mgemm_kernel(
    const float* __restrict__ A, const float* __restrict__ Bw,
    const float* __restrict__ bias, const float* __restrict__ res,
    float* __restrict__ C, int Nout, int K)
{
    extern __shared__ float sm[];
    int tid  = threadIdx.x;
    int wid  = tid >> 5, lane = tid & 31;
    int wm   = wid >> 2, wn = wid & 3;
    int g    = lane >> 2, t4 = lane & 3;
    int m0   = blockIdx.y * 128;
    int n0   = blockIdx.x * 256;
    uint32_t sbase = smem_u32(sm);

    float acc[4][8][4];
    #pragma unroll
    for (int i = 0; i < 4; ++i)
        #pragma unroll
        for (int j = 0; j < 8; ++j)
            #pragma unroll
            for (int k = 0; k < 4; ++k) acc[i][j][k] = 0.0f;

    const int T = K >> 5;

    auto issue = [&](int kt, int s) {
        uint32_t ab = sbase + (uint32_t)(s * STAGE_ELEMS) * 4u;
        uint32_t bb = ab + (uint32_t)A_ELEMS * 4u;
        int k0 = kt << 5;
        #pragma unroll
        for (int i = 0; i < 4; ++i) {
            int c = tid + i * 256;
            int row = c >> 3, cc = c & 7;
            CP_ASYNC16(ab + (uint32_t)(row * LDT + cc * 4) * 4u,
                       A + (size_t)(m0 + row) * K + k0 + cc * 4);
        }
        #pragma unroll
        for (int i = 0; i < 8; ++i) {
            int c = tid + i * 256;
            int row = c >> 3, cc = c & 7;
            CP_ASYNC16(bb + (uint32_t)(row * LDT + cc * 4) * 4u,
                       Bw + (size_t)(n0 + row) * K + k0 + cc * 4);
        }
        CP_COMMIT();
    };

    issue(0, 0); issue(1, 1); issue(2, 2);

    int s = 0;
    for (int t = 0; t < T; ++t) {
        CP_WAIT2();
        __syncthreads();
        const float* As = sm + s * STAGE_ELEMS;
        const float* Bs = As + A_ELEMS;

        #pragma unroll
        for (int kk = 0; kk < 32; kk += 8) {
            uint32_t af[4][4], bf[8][2];
            #pragma unroll
            for (int mt = 0; mt < 4; ++mt) {
                int r = wm * 64 + mt * 16 + g;
                af[mt][0] = f2tf(As[r * LDT + kk + t4]);
                af[mt][1] = f2tf(As[(r + 8) * LDT + kk + t4]);
                af[mt][2] = f2tf(As[r * LDT + kk + t4 + 4]);
                af[mt][3] = f2tf(As[(r + 8) * LDT + kk + t4 + 4]);
            }
            #pragma unroll
            for (int nt = 0; nt < 8; ++nt) {
                int n = wn * 64 + nt * 8 + g;
                bf[nt][0] = f2tf(Bs[n * LDT + kk + t4]);
                bf[nt][1] = f2tf(Bs[n * LDT + kk + t4 + 4]);
            }
            #pragma unroll
            for (int mt = 0; mt < 4; ++mt)
                #pragma unroll
                for (int nt = 0; nt < 8; ++nt)
                    mma_tf32(acc[mt][nt], af[mt], bf[nt]);
        }
        __syncthreads();
        if (t + 3 < T) issue(t + 3, s); else CP_COMMIT();
        if (++s == 3) s = 0;
    }

    // ---- epilogue ----
    const float kS = 0.70710678118654752440f;
    #pragma unroll
    for (int mt = 0; mt < 4; ++mt) {
        #pragma unroll
        for (int rr = 0; rr < 2; ++rr) {
            int m  = m0 + wm * 64 + mt * 16 + g + rr * 8;
            int dm = (EPI == 3) ? win_to_pix(m) : m;
            float*       crow = C + (size_t)dm * Nout + n0 + wn * 64;
            const float* rrow = (EPI >= 2) ? res + (size_t)dm * Nout + n0 + wn * 64 : nullptr;
            const float* brow = bias + n0 + wn * 64;
            #pragma unroll
            for (int nt = 0; nt < 8; ++nt) {
                int col = nt * 8 + t4 * 2;
                float v0 = acc[mt][nt][rr * 2 + 0] + brow[col];
                float v1 = acc[mt][nt][rr * 2 + 1] + brow[col + 1];
                if (EPI == 1) {
                    v0 = 0.5f * v0 * (1.0f + erff(v0 * kS));
                    v1 = 0.5f * v1 * (1.0f + erff(v1 * kS));
                }
                if (EPI >= 2) { v0 += rrow[col]; v1 += rrow[col + 1]; }
                *(float2*)(crow + col) = make_float2(v0, v1);
            }
        }
    }
}

// ---------------- windowed attention: one CTA per (window, head) ------------
__global__ __launch_bounds__(256) void attn_kernel(
    const float* __restrict__ qkv, const float* __restrict__ rpb,
    const int* __restrict__ rel_idx, const float* __restrict__ mask,
    float* __restrict__ out)
{
    __shared__ float sq[NTOK][HD];
    __shared__ float sk[NTOK][HD];
    __shared__ float sv[NTOK][HD];
    __shared__ float S[NTOK][NTOK];

    int blk = blockIdx.x;
    int h   = blk & (HEADS - 1);
    int wv  = blk >> 3;
    int wi  = wv & (NWIN - 1);
    int tid = threadIdx.x;
    const float scale = 0.17677669529663688f;

    for (int idx = tid; idx < NTOK * HD; idx += 256) {
        int n = idx >> 5, d = idx & 31;
        size_t base = (size_t)(wv * NTOK + n) * 768 + h * HD + d;
        sq[n][d] = qkv[base] * scale;
        sk[n][d] = qkv[base + 256];
        sv[n][d] = qkv[base + 512];
    }
    __syncthreads();

    for (int idx = tid; idx < NTOK * NTOK; idx += 256) {
        int n = idx / NTOK, m = idx - n * NTOK;
        float a = 0.0f;
        #pragma unroll
        for (int d = 0; d < HD; ++d) a += sq[n][d] * sk[m][d];
        a += rpb[rel_idx[idx] * HEADS + h];
        a += mask[(size_t)wi * (NTOK * NTOK) + idx];
        S[n][m] = a;
    }
    __syncthreads();

    int warp = tid >> 5, lane = tid & 31;
    for (int r = warp; r < NTOK; r += 8) {
        float mx = -1e30f;
        for (int m = lane; m < NTOK; m += 32) mx = fmaxf(mx, S[r][m]);
        #pragma unroll
        for (int o = 16; o; o >>= 1) mx = fmaxf(mx, __shfl_xor_sync(0xffffffffu, mx, o));
        float sum = 0.0f;
        for (int m = lane; m < NTOK; m += 32) {
            float e = __expf(S[r][m] - mx);
            S[r][m] = e;
            sum += e;
        }
        #pragma unroll
        for (int o = 16; o; o >>= 1) sum += __shfl_xor_sync(0xffffffffu, sum, o);
        float inv = 1.0f / sum;
        for (int m = lane; m < NTOK; m += 32) S[r][m] *= inv;
    }
    __syncthreads();

    for (int idx = tid; idx < NTOK * HD; idx += 256) {
        int n = idx >> 5, d = idx & 31;
        float a = 0.0f;
        #pragma unroll
        for (int m = 0; m < NTOK; ++m) a += S[n][m] * sv[m][d];
        out[(size_t)(wv * NTOK + n) * DIM + h * HD + d] = a;
    }
}

// ---------------- launch --------------------------------------------------
extern "C" void kernel_launch(void* const* d_in, const int* in_sizes, int n_in,
                              void* d_out, int out_size) {
    const float* x     = (const float*)d_in[0];
    const float* n1w   = (const float*)d_in[1];
    const float* n1b   = (const float*)d_in[2];
    const float* qkvw  = (const float*)d_in[3];
    const float* qkvb  = (const float*)d_in[4];
    const float* rpb   = (const float*)d_in[5];
    const float* projw = (const float*)d_in[6];
    const float* projb = (const float*)d_in[7];
    const float* n2w   = (const float*)d_in[8];
    const float* n2b   = (const float*)d_in[9];
    const float* fc1w  = (const float*)d_in[10];
    const float* fc1b  = (const float*)d_in[11];
    const float* fc2w  = (const float*)d_in[12];
    const float* fc2b  = (const float*)d_in[13];
    const int*   relix = (const int*)d_in[14];
    const float* mask  = (const float*)d_in[15];
    float* out = (float*)d_out;

    float *bufA, *bufB, *bufX;
    cudaGetSymbolAddress((void**)&bufA, g_bufA);
    cudaGetSymbolAddress((void**)&bufB, g_bufB);
    cudaGetSymbolAddress((void**)&bufX, g_bufX);

    const int LN_BLOCKS = T_TOK / 8;       // 12544
    const int MT = T_TOK / 128;            // 784
    const int SHMEM = 3 * STAGE_ELEMS * 4; // 165888 bytes

    static bool attr_set = false;
    cudaFuncSetAttribute(mgemm_kernel<0>, cudaFuncAttributeMaxDynamicSharedMemorySize, SHMEM);
    cudaFuncSetAttribute(mgemm_kernel<1>, cudaFuncAttributeMaxDynamicSharedMemorySize, SHMEM);
    cudaFuncSetAttribute(mgemm_kernel<2>, cudaFuncAttributeMaxDynamicSharedMemorySize, SHMEM);
    cudaFuncSetAttribute(mgemm_kernel<3>, cudaFuncAttributeMaxDynamicSharedMemorySize, SHMEM);
    attr_set = true; (void)attr_set;

    // 1) LN1 + cyclic shift + window partition  (x -> bufB, window order)
    ln_kernel<1><<<LN_BLOCKS, 256>>>(x, n1w, n1b, bufB);

    // 2) qkv = hwin @ qkv_w^T + b   -> bufA [T,768]
    mgemm_kernel<0><<<dim3(768 / 256, MT), 256, SHMEM>>>(bufB, qkvw, qkvb, nullptr, bufA, 768, DIM);

    // 3) windowed attention -> bufB [T,256] (window order)
    attn_kernel<<<(T_TOK / NTOK) * HEADS, 256>>>(bufA, rpb, relix, mask, bufB);

    // 4) proj + window-reverse + un-shift + residual -> bufX (pixel order)
    mgemm_kernel<3><<<dim3(DIM / 256, MT), 256, SHMEM>>>(bufB, projw, projb, x, bufX, DIM, DIM);

    // 5) LN2 (bufX -> bufB, token order)
    ln_kernel<0><<<LN_BLOCKS, 256>>>(bufX, n2w, n2b, bufB);

    // 6) fc1 + exact GELU -> bufA [T,1024]
    mgemm_kernel<1><<<dim3(HIDDEN / 256, MT), 256, SHMEM>>>(bufB, fc1w, fc1b, nullptr, bufA, HIDDEN, DIM);

    // 7) fc2 + residual -> d_out
    mgemm_kernel<2><<<dim3(DIM / 256, MT), 256, SHMEM>>>(bufA, fc2w, fc2b, bufX, out, DIM, HIDDEN);
}

// round 4
// speedup vs baseline: 3.3840x; 2.9570x over previous
#include <cuda_runtime.h>
#include <cstdint>
#include <math.h>

// ---------------- problem constants ----------------
#define BATCH   32
#define HH      56
#define WIMG    56
#define DIM     256
#define HEADS   8
#define HD      32
#define WS      7
#define SHIFT   3
#define NTOK    49
#define NWIN    64
#define HIDDEN  1024
#define T_TOK   100352

// ---------------- scratch ----------------
__device__ float g_bufA[(size_t)T_TOK * 1024];   // qkv [T,768] / fc1-out [T,1024]
__device__ float g_bufB[(size_t)T_TOK * 256];    // LN1-out / attn-out (tf32 bits)
__device__ float g_bufC[(size_t)T_TOK * 256];    // LN2-out (tf32 bits)
__device__ float g_bufX[(size_t)T_TOK * 256];    // x after first residual (fp32)
__device__ float g_bufW[786432];                 // tf32 weights: qkv|proj|fc1|fc2

// ---------------- helpers ----------------
__device__ __forceinline__ uint32_t smem_u32(const void* p) {
    uint32_t a;
    asm("{ .reg .u64 t; cvta.to.shared.u64 t, %1; cvt.u32.u64 %0, t; }" : "=r"(a) : "l"(p));
    return a;
}
#define CP_ASYNC16(dst, src) \
    asm volatile("cp.async.cg.shared.global [%0], [%1], 16;\n" :: "r"(dst), "l"(src))
#define CP_COMMIT() asm volatile("cp.async.commit_group;\n" ::: "memory")
#define CP_WAIT2()  asm volatile("cp.async.wait_group 2;\n" ::: "memory")

__device__ __forceinline__ uint32_t f2tf(float x) {
    uint32_t r;
    asm("cvt.rna.tf32.f32 %0, %1;" : "=r"(r) : "f"(x));
    return r;
}
__device__ __forceinline__ float f2tff(float x) { return __uint_as_float(f2tf(x)); }

__device__ __forceinline__ void mma_tf32(float* d, const uint32_t* a, const uint32_t* b) {
    asm volatile(
        "mma.sync.aligned.m16n8k8.row.col.f32.tf32.tf32.f32 "
        "{%0,%1,%2,%3}, {%4,%5,%6,%7}, {%8,%9}, {%0,%1,%2,%3};"
        : "+f"(d[0]), "+f"(d[1]), "+f"(d[2]), "+f"(d[3])
        : "r"(a[0]), "r"(a[1]), "r"(a[2]), "r"(a[3]), "r"(b[0]), "r"(b[1]));
}

__device__ __forceinline__ int win_to_pix(int m) {
    int n_in = m % NTOK;
    int wv   = m / NTOK;
    int bimg = wv >> 6;
    int wi   = wv & 63;
    int wh   = wi >> 3;
    int wc   = wi & 7;
    int i    = n_in / WS;
    int j    = n_in - i * WS;
    int pr   = wh * WS + i + SHIFT; if (pr >= HH)   pr -= HH;
    int pc   = wc * WS + j + SHIFT; if (pc >= WIMG) pc -= WIMG;
    return bimg * (HH * WIMG) + pr * WIMG + pc;
}

// ---------------- weight -> tf32 conversion ----------------
__global__ void convw_kernel(const float* __restrict__ s, float* __restrict__ d, int n) {
    int i = blockIdx.x * 256 + threadIdx.x;
    if (i < n) d[i] = f2tff(s[i]);
}

// ---------------- LayerNorm + shift + window gather, tf32 output ------------
__global__ __launch_bounds__(256) void ln_kernel(
    const float* __restrict__ x, const float* __restrict__ w,
    const float* __restrict__ b, float* __restrict__ out)
{
    int t    = blockIdx.x * 8 + (threadIdx.x >> 5);
    int lane = threadIdx.x & 31;
    int src  = win_to_pix(t);

    const float4* px = (const float4*)(x + (size_t)src * DIM) + lane * 2;
    float4 v0 = px[0], v1 = px[1];

    float s  = v0.x + v0.y + v0.z + v0.w + v1.x + v1.y + v1.z + v1.w;
    float ss = v0.x*v0.x + v0.y*v0.y + v0.z*v0.z + v0.w*v0.w
             + v1.x*v1.x + v1.y*v1.y + v1.z*v1.z + v1.w*v1.w;
    #pragma unroll
    for (int o = 16; o; o >>= 1) {
        s  += __shfl_xor_sync(0xffffffffu, s,  o);
        ss += __shfl_xor_sync(0xffffffffu, ss, o);
    }
    float mean = s * (1.0f / DIM);
    float var  = ss * (1.0f / DIM) - mean * mean;
    float rstd = rsqrtf(var + 1e-5f);

    int c0 = lane * 8;
    const float4* pw = (const float4*)(w + c0);
    const float4* pb = (const float4*)(b + c0);
    float4 w0 = pw[0], w1 = pw[1], b0 = pb[0], b1 = pb[1];
    float4 o0, o1;
    o0.x = f2tff((v0.x - mean) * rstd * w0.x + b0.x);
    o0.y = f2tff((v0.y - mean) * rstd * w0.y + b0.y);
    o0.z = f2tff((v0.z - mean) * rstd * w0.z + b0.z);
    o0.w = f2tff((v0.w - mean) * rstd * w0.w + b0.w);
    o1.x = f2tff((v1.x - mean) * rstd * w1.x + b1.x);
    o1.y = f2tff((v1.y - mean) * rstd * w1.y + b1.y);
    o1.z = f2tff((v1.z - mean) * rstd * w1.z + b1.z);
    o1.w = f2tff((v1.w - mean) * rstd * w1.w + b1.w);
    float4* po = (float4*)(out + (size_t)t * DIM) + lane * 2;
    po[0] = o0; po[1] = o1;
}

// ---------------- tf32 mma GEMM, CTA 128x256, 16 warps of 64x32, BK=32 ------
// EPI: 0 none | 1 GELU->tf32 | 2 +res (final out) | 3 +res scatter + fused LN2
#define BM 128
#define BN 256
#define LDT 36
#define A_ELEMS (BM * LDT)
#define B_ELEMS (BN * LDT)
#define STAGE_ELEMS (A_ELEMS + B_ELEMS)   // 13824 floats

template<int EPI>
__global__ __launch_bounds__(512, 1) void mgemm_kernel(
    const float* __restrict__ A, const float* __restrict__ Bw,
    const float* __restrict__ bias, const float* __restrict__ res,
    float* __restrict__ C, float* __restrict__ Cln,
    const float* __restrict__ lnw, const float* __restrict__ lnb,
    int Nout, int K)
{
    extern __shared__ float sm[];
    int tid  = threadIdx.x;
    int wid  = tid >> 5, lane = tid & 31;
    int wm   = wid >> 3, wn = wid & 7;       // 2 x 8 warps
    int g    = lane >> 2, t4 = lane & 3;
    int m0   = blockIdx.y * BM;
    int n0   = blockIdx.x * BN;
    uint32_t sbase = smem_u32(sm);

    float acc[4][4][4];
    #pragma unroll
    for (int i = 0; i < 4; ++i)
        #pragma unroll
        for (int j = 0; j < 4; ++j)
            #pragma unroll
            for (int k = 0; k < 4; ++k) acc[i][j][k] = 0.0f;

    const int T = K >> 5;

    auto issue = [&](int kt, int s) {
        uint32_t ab = sbase + (uint32_t)(s * STAGE_ELEMS) * 4u;
        uint32_t bb = ab + (uint32_t)A_ELEMS * 4u;
        int k0 = kt << 5;
        #pragma unroll
        for (int i = 0; i < 2; ++i) {
            int c = tid + i * 512;
            int row = c >> 3, cc = c & 7;
            CP_ASYNC16(ab + (uint32_t)(row * LDT + cc * 4) * 4u,
                       A + (size_t)(m0 + row) * K + k0 + cc * 4);
        }
        #pragma unroll
        for (int i = 0; i < 4; ++i) {
            int c = tid + i * 512;
            int row = c >> 3, cc = c & 7;
            CP_ASYNC16(bb + (uint32_t)(row * LDT + cc * 4) * 4u,
                       Bw + (size_t)(n0 + row) * K + k0 + cc * 4);
        }
        CP_COMMIT();
    };

    issue(0, 0); issue(1, 1); issue(2, 2);

    int s = 0;
    for (int t = 0; t < T; ++t) {
        CP_WAIT2();
        __syncthreads();
        const float* As = sm + s * STAGE_ELEMS;
        const float* Bs = As + A_ELEMS;

        #pragma unroll
        for (int kk = 0; kk < 32; kk += 8) {
            uint32_t af[4][4], bf[4][2];
            #pragma unroll
            for (int mt = 0; mt < 4; ++mt) {
                int r = wm * 64 + mt * 16 + g;
                af[mt][0] = __float_as_uint(As[r * LDT + kk + t4]);
                af[mt][1] = __float_as_uint(As[(r + 8) * LDT + kk + t4]);
                af[mt][2] = __float_as_uint(As[r * LDT + kk + t4 + 4]);
                af[mt][3] = __float_as_uint(As[(r + 8) * LDT + kk + t4 + 4]);
            }
            #pragma unroll
            for (int nt = 0; nt < 4; ++nt) {
                int n = wn * 32 + nt * 8 + g;
                bf[nt][0] = __float_as_uint(Bs[n * LDT + kk + t4]);
                bf[nt][1] = __float_as_uint(Bs[n * LDT + kk + t4 + 4]);
            }
            #pragma unroll
            for (int mt = 0; mt < 4; ++mt)
                #pragma unroll
                for (int nt = 0; nt < 4; ++nt)
                    mma_tf32(acc[mt][nt], af[mt], bf[nt]);
        }
        __syncthreads();
        if (t + 3 < T) issue(t + 3, s); else CP_COMMIT();
        if (++s == 3) s = 0;
    }

    const float kS = 0.70710678118654752440f;

    if (EPI == 3) {
        // proj: v = acc + bias + res[pix]; write bufX(v); fused LN2 -> Cln (tf32)
        __syncthreads();
        float2* p2      = (float2*)sm;          // 512*8 partials
        float2* rowstat = ((float2*)sm) + 4096; // 128 rows

        #pragma unroll
        for (int mt = 0; mt < 4; ++mt) {
            #pragma unroll
            for (int rr = 0; rr < 2; ++rr) {
                int lm = wm * 64 + mt * 16 + rr * 8 + g;
                int dm = win_to_pix(m0 + lm);
                float*       xrow = C   + (size_t)dm * Nout;
                const float* rrow = res + (size_t)dm * Nout;
                float psum = 0.0f, psq = 0.0f;
                #pragma unroll
                for (int nt = 0; nt < 4; ++nt) {
                    int col = wn * 32 + nt * 8 + t4 * 2;
                    float v0 = acc[mt][nt][rr * 2 + 0] + bias[col]     + rrow[col];
                    float v1 = acc[mt][nt][rr * 2 + 1] + bias[col + 1] + rrow[col + 1];
                    acc[mt][nt][rr * 2 + 0] = v0;
                    acc[mt][nt][rr * 2 + 1] = v1;
                    *(float2*)(xrow + col) = make_float2(v0, v1);
                    psum += v0 + v1; psq += v0 * v0 + v1 * v1;
                }
                p2[tid * 8 + mt * 2 + rr] = make_float2(psum, psq);
            }
        }
        __syncthreads();
        if (tid < 128) {
            int lm = tid;
            int lwm = lm >> 6, lmt = (lm >> 4) & 3, lrr = (lm >> 3) & 1, lg = lm & 7;
            float s1 = 0.0f, s2 = 0.0f;
            #pragma unroll
            for (int w = 0; w < 8; ++w)
                #pragma unroll
                for (int q = 0; q < 4; ++q) {
                    float2 f = p2[(((lwm * 8 + w) << 5) + (lg << 2) + q) * 8 + lmt * 2 + lrr];
                    s1 += f.x; s2 += f.y;
                }
            float mean = s1 * (1.0f / 256.0f);
            float var  = s2 * (1.0f / 256.0f) - mean * mean;
            rowstat[lm] = make_float2(mean, rsqrtf(var + 1e-5f));
        }
        __syncthreads();
        #pragma unroll
        for (int mt = 0; mt < 4; ++mt) {
            #pragma unroll
            for (int rr = 0; rr < 2; ++rr) {
                int lm = wm * 64 + mt * 16 + rr * 8 + g;
                float2 st = rowstat[lm];
                int dm = win_to_pix(m0 + lm);
                float* lrow = Cln + (size_t)dm * Nout;
                #pragma unroll
                for (int nt = 0; nt < 4; ++nt) {
                    int col = wn * 32 + nt * 8 + t4 * 2;
                    float v0 = f2tff((acc[mt][nt][rr * 2 + 0] - st.x) * st.y * lnw[col]     + lnb[col]);
                    float v1 = f2tff((acc[mt][nt][rr * 2 + 1] - st.x) * st.y * lnw[col + 1] + lnb[col + 1]);
                    *(float2*)(lrow + col) = make_float2(v0, v1);
                }
            }
        }
        return;
    }

    #pragma unroll
    for (int mt = 0; mt < 4; ++mt) {
        #pragma unroll
        for (int rr = 0; rr < 2; ++rr) {
            int m = m0 + wm * 64 + mt * 16 + rr * 8 + g;
            float*       crow = C + (size_t)m * Nout + n0;
            const float* rrow = (EPI == 2) ? res + (size_t)m * Nout + n0 : nullptr;
            #pragma unroll
            for (int nt = 0; nt < 4; ++nt) {
                int col = wn * 32 + nt * 8 + t4 * 2;
                float v0 = acc[mt][nt][rr * 2 + 0] + bias[n0 + col];
                float v1 = acc[mt][nt][rr * 2 + 1] + bias[n0 + col + 1];
                if (EPI == 1) {
                    v0 = f2tff(0.5f * v0 * (1.0f + erff(v0 * kS)));
                    v1 = f2tff(0.5f * v1 * (1.0f + erff(v1 * kS)));
                }
                if (EPI == 2) { v0 += rrow[col]; v1 += rrow[col + 1]; }
                *(float2*)(crow + col) = make_float2(v0, v1);
            }
        }
    }
}

// ---------------- attention: CTA per (window, head), 128 threads ------------
__global__ __launch_bounds__(128) void attn_kernel(
    const float* __restrict__ qkv, const float* __restrict__ rpb,
    const int* __restrict__ rel_idx, const float* __restrict__ mask,
    float* __restrict__ out)
{
    __shared__ float sq[NTOK][33];
    __shared__ float sk[NTOK][33];
    __shared__ float sv[NTOK][33];
    __shared__ float S[NTOK][50];

    int blk = blockIdx.x;
    int h   = blk & (HEADS - 1);
    int wv  = blk >> 3;
    int wi  = wv & (NWIN - 1);
    int tid = threadIdx.x;
    int a   = tid >> 4;      // 0..7   (row phase)
    int b   = tid & 15;      // 0..15  (col phase)
    const float scale = 0.17677669529663688f;

    for (int idx = tid; idx < NTOK * HD; idx += 128) {
        int n = idx >> 5, d = idx & 31;
        size_t base = (size_t)(wv * NTOK + n) * 768 + h * HD + d;
        sq[n][d] = qkv[base] * scale;
        sk[n][d] = qkv[base + 256];
        sv[n][d] = qkv[base + 512];
    }
    __syncthreads();

    // S = q k^T, register tiled 7 x 4 per thread
    {
        float acc[7][4];
        #pragma unroll
        for (int i = 0; i < 7; ++i)
            #pragma unroll
            for (int j = 0; j < 4; ++j) acc[i][j] = 0.0f;

        #pragma unroll 8
        for (int d = 0; d < HD; ++d) {
            float qd[7], kd[4];
            #pragma unroll
            for (int i = 0; i < 7; ++i) {
                int n = a + 8 * i;
                qd[i] = (n < NTOK) ? sq[n][d] : 0.0f;
            }
            #pragma unroll
            for (int j = 0; j < 4; ++j) {
                int m = b + 16 * j;
                kd[j] = (m < NTOK) ? sk[m][d] : 0.0f;
            }
            #pragma unroll
            for (int i = 0; i < 7; ++i)
                #pragma unroll
                for (int j = 0; j < 4; ++j) acc[i][j] += qd[i] * kd[j];
        }
        const float* mrow = mask + (size_t)wi * (NTOK * NTOK);
        #pragma unroll
        for (int i = 0; i < 7; ++i) {
            int n = a + 8 * i;
            if (n >= NTOK) break;
            #pragma unroll
            for (int j = 0; j < 4; ++j) {
                int m = b + 16 * j;
                if (m < NTOK) {
                    int e = n * NTOK + m;
                    S[n][m] = acc[i][j] + rpb[rel_idx[e] * HEADS + h] + mrow[e];
                }
            }
        }
    }
    __syncthreads();

    // softmax: warp per row
    int warp = tid >> 5, lane = tid & 31;
    for (int r = warp; r < NTOK; r += 4) {
        float mx = -1e30f;
        for (int m = lane; m < NTOK; m += 32) mx = fmaxf(mx, S[r][m]);
        #pragma unroll
        for (int o = 16; o; o >>= 1) mx = fmaxf(mx, __shfl_xor_sync(0xffffffffu, mx, o));
        float sum = 0.0f;
        for (int m = lane; m < NTOK; m += 32) {
            float e = __expf(S[r][m] - mx);
            S[r][m] = e;
            sum += e;
        }
        #pragma unroll
        for (int o = 16; o; o >>= 1) sum += __shfl_xor_sync(0xffffffffu, sum, o);
        float inv = 1.0f / sum;
        for (int m = lane; m < NTOK; m += 32) S[r][m] *= inv;
    }
    __syncthreads();

    // out = S @ V, 7 rows x 2 cols per thread
    {
        float o0[7], o1[7];
        #pragma unroll
        for (int i = 0; i < 7; ++i) { o0[i] = 0.0f; o1[i] = 0.0f; }
        int d0 = b * 2;
        for (int m = 0; m < NTOK; ++m) {
            float v0 = sv[m][d0], v1 = sv[m][d0 + 1];
            #pragma unroll
            for (int i = 0; i < 7; ++i) {
                int n = a + 8 * i;
                float sv_ = (n < NTOK) ? S[n][m] : 0.0f;
                o0[i] += sv_ * v0;
                o1[i] += sv_ * v1;
            }
        }
        #pragma unroll
        for (int i = 0; i < 7; ++i) {
            int n = a + 8 * i;
            if (n < NTOK) {
                float* orow = out + (size_t)(wv * NTOK + n) * DIM + h * HD + d0;
                orow[0] = f2tff(o0[i]);
                orow[1] = f2tff(o1[i]);
            }
        }
    }
}

// ---------------- launch --------------------------------------------------
extern "C" void kernel_launch(void* const* d_in, const int* in_sizes, int n_in,
                              void* d_out, int out_size) {
    const float* x     = (const float*)d_in[0];
    const float* n1w   = (const float*)d_in[1];
    const float* n1b   = (const float*)d_in[2];
    const float* qkvw  = (const float*)d_in[3];
    const float* qkvb  = (const float*)d_in[4];
    const float* rpb   = (const float*)d_in[5];
    const float* projw = (const float*)d_in[6];
    const float* projb = (const float*)d_in[7];
    const float* n2w   = (const float*)d_in[8];
    const float* n2b   = (const float*)d_in[9];
    const float* fc1w  = (const float*)d_in[10];
    const float* fc1b  = (const float*)d_in[11];
    const float* fc2w  = (const float*)d_in[12];
    const float* fc2b  = (const float*)d_in[13];
    const int*   relix = (const int*)d_in[14];
    const float* mask  = (const float*)d_in[15];
    float* out = (float*)d_out;

    float *bufA, *bufB, *bufC, *bufX, *bufW;
    cudaGetSymbolAddress((void**)&bufA, g_bufA);
    cudaGetSymbolAddress((void**)&bufB, g_bufB);
    cudaGetSymbolAddress((void**)&bufC, g_bufC);
    cudaGetSymbolAddress((void**)&bufX, g_bufX);
    cudaGetSymbolAddress((void**)&bufW, g_bufW);

    float* wqkv = bufW;                 // 768*256  = 196608
    float* wprj = wqkv + 196608;        // 256*256  =  65536
    float* wfc1 = wprj + 65536;         // 1024*256 = 262144
    float* wfc2 = wfc1 + 262144;        // 256*1024 = 262144

    const int LN_BLOCKS = T_TOK / 8;
    const int MT = T_TOK / BM;          // 784
    const int SHMEM = 3 * STAGE_ELEMS * 4;  // 165888

    cudaFuncSetAttribute(mgemm_kernel<0>, cudaFuncAttributeMaxDynamicSharedMemorySize, SHMEM);
    cudaFuncSetAttribute(mgemm_kernel<1>, cudaFuncAttributeMaxDynamicSharedMemorySize, SHMEM);
    cudaFuncSetAttribute(mgemm_kernel<2>, cudaFuncAttributeMaxDynamicSharedMemorySize, SHMEM);
    cudaFuncSetAttribute(mgemm_kernel<3>, cudaFuncAttributeMaxDynamicSharedMemorySize, SHMEM);

    // 0) convert weights to tf32
    convw_kernel<<<(196608 + 255) / 256, 256>>>(qkvw, wqkv, 196608);
    convw_kernel<<<(65536  + 255) / 256, 256>>>(projw, wprj, 65536);
    convw_kernel<<<(262144 + 255) / 256, 256>>>(fc1w, wfc1, 262144);
    convw_kernel<<<(262144 + 255) / 256, 256>>>(fc2w, wfc2, 262144);

    // 1) LN1 + shift + window partition -> bufB (tf32)
    ln_kernel<<<LN_BLOCKS, 256>>>(x, n1w, n1b, bufB);

    // 2) qkv GEMM -> bufA [T,768]
    mgemm_kernel<0><<<dim3(768 / BN, MT), 512, SHMEM>>>(
        bufB, wqkv, qkvb, nullptr, bufA, nullptr, nullptr, nullptr, 768, DIM);

    // 3) attention -> bufB (tf32, window order)
    attn_kernel<<<(T_TOK / NTOK) * HEADS, 128>>>(bufA, rpb, relix, mask, bufB);

    // 4) proj + scatter + residual + fused LN2 -> bufX (fp32), bufC (tf32)
    mgemm_kernel<3><<<dim3(1, MT), 512, SHMEM>>>(
        bufB, wprj, projb, x, bufX, bufC, n2w, n2b, DIM, DIM);

    // 5) fc1 + GELU -> bufA [T,1024] (tf32)
    mgemm_kernel<1><<<dim3(HIDDEN / BN, MT), 512, SHMEM>>>(
        bufC, wfc1, fc1b, nullptr, bufA, nullptr, nullptr, nullptr, HIDDEN, DIM);

    // 6) fc2 + residual -> d_out
    mgemm_kernel<2><<<dim3(1, MT), 512, SHMEM>>>(
        bufA, wfc2, fc2b, bufX, out, nullptr, nullptr, nullptr, DIM, HIDDEN);
}

// round 5
// speedup vs baseline: 4.4476x; 1.3143x over previous
#include <cuda_runtime.h>
#include <cuda_bf16.h>
#include <cstdint>
#include <math.h>

// ---------------- problem constants ----------------
#define BATCH   32
#define HH      56
#define WIMG    56
#define DIM     256
#define HEADS   8
#define HD      32
#define WS      7
#define SHIFT   3
#define NTOK    49
#define NWIN    64
#define HIDDEN  1024
#define T_TOK   100352

// ---------------- scratch ----------------
__device__ __nv_bfloat16 g_bufA[(size_t)T_TOK * 1024]; // qkv [T,768] / fc1-out [T,1024]
__device__ __nv_bfloat16 g_bufB[(size_t)T_TOK * 256];  // LN1-out / attn-out
__device__ __nv_bfloat16 g_bufC[(size_t)T_TOK * 256];  // LN2-out
__device__ float         g_bufX[(size_t)T_TOK * 256];  // x after first residual (fp32)
__device__ __nv_bfloat16 g_bufW[786432];               // bf16 weights: qkv|proj|fc1|fc2

// ---------------- helpers ----------------
__device__ __forceinline__ uint32_t smem_u32(const void* p) {
    uint32_t a;
    asm("{ .reg .u64 t; cvta.to.shared.u64 t, %1; cvt.u32.u64 %0, t; }" : "=r"(a) : "l"(p));
    return a;
}
#define CP_ASYNC16(dst, src) \
    asm volatile("cp.async.cg.shared.global [%0], [%1], 16;\n" :: "r"(dst), "l"(src))
#define CP_COMMIT() asm volatile("cp.async.commit_group;\n" ::: "memory")
#define CP_WAIT2()  asm volatile("cp.async.wait_group 2;\n" ::: "memory")

// D[16x8] += A[16x16] * B[16x8]; bf16 inputs, f32 accumulate
__device__ __forceinline__ void mma_bf16(float* d, const uint32_t* a, const uint32_t* b) {
    asm volatile(
        "mma.sync.aligned.m16n8k16.row.col.f32.bf16.bf16.f32 "
        "{%0,%1,%2,%3}, {%4,%5,%6,%7}, {%8,%9}, {%0,%1,%2,%3};"
        : "+f"(d[0]), "+f"(d[1]), "+f"(d[2]), "+f"(d[3])
        : "r"(a[0]), "r"(a[1]), "r"(a[2]), "r"(a[3]), "r"(b[0]), "r"(b[1]));
}

__device__ __forceinline__ int win_to_pix(int m) {
    int n_in = m % NTOK;
    int wv   = m / NTOK;
    int bimg = wv >> 6;
    int wi   = wv & 63;
    int wh   = wi >> 3;
    int wc   = wi & 7;
    int i    = n_in / WS;
    int j    = n_in - i * WS;
    int pr   = wh * WS + i + SHIFT; if (pr >= HH)   pr -= HH;
    int pc   = wc * WS + j + SHIFT; if (pc >= WIMG) pc -= WIMG;
    return bimg * (HH * WIMG) + pr * WIMG + pc;
}

// ---------------- weight -> bf16 conversion ----------------
__global__ void convw_kernel(const float* __restrict__ s, __nv_bfloat16* __restrict__ d, int n) {
    int i = blockIdx.x * 256 + threadIdx.x;
    if (i < n) d[i] = __float2bfloat16_rn(s[i]);
}

// ---------------- LayerNorm + shift + window gather, bf16 output ------------
__global__ __launch_bounds__(256) void ln_kernel(
    const float* __restrict__ x, const float* __restrict__ w,
    const float* __restrict__ b, __nv_bfloat16* __restrict__ out)
{
    int t    = blockIdx.x * 8 + (threadIdx.x >> 5);
    int lane = threadIdx.x & 31;
    int src  = win_to_pix(t);

    const float4* px = (const float4*)(x + (size_t)src * DIM) + lane * 2;
    float4 v0 = px[0], v1 = px[1];

    float s  = v0.x + v0.y + v0.z + v0.w + v1.x + v1.y + v1.z + v1.w;
    float ss = v0.x*v0.x + v0.y*v0.y + v0.z*v0.z + v0.w*v0.w
             + v1.x*v1.x + v1.y*v1.y + v1.z*v1.z + v1.w*v1.w;
    #pragma unroll
    for (int o = 16; o; o >>= 1) {
        s  += __shfl_xor_sync(0xffffffffu, s,  o);
        ss += __shfl_xor_sync(0xffffffffu, ss, o);
    }
    float mean = s * (1.0f / DIM);
    float var  = ss * (1.0f / DIM) - mean * mean;
    float rstd = rsqrtf(var + 1e-5f);

    int c0 = lane * 8;
    const float4* pw = (const float4*)(w + c0);
    const float4* pb = (const float4*)(b + c0);
    float4 w0 = pw[0], w1 = pw[1], b0 = pb[0], b1 = pb[1];

    union { __nv_bfloat162 h2[4]; uint4 u; } pk;
    pk.h2[0] = __floats2bfloat162_rn((v0.x - mean) * rstd * w0.x + b0.x,
                                     (v0.y - mean) * rstd * w0.y + b0.y);
    pk.h2[1] = __floats2bfloat162_rn((v0.z - mean) * rstd * w0.z + b0.z,
                                     (v0.w - mean) * rstd * w0.w + b0.w);
    pk.h2[2] = __floats2bfloat162_rn((v1.x - mean) * rstd * w1.x + b1.x,
                                     (v1.y - mean) * rstd * w1.y + b1.y);
    pk.h2[3] = __floats2bfloat162_rn((v1.z - mean) * rstd * w1.z + b1.z,
                                     (v1.w - mean) * rstd * w1.w + b1.w);
    *(uint4*)(out + (size_t)t * DIM + c0) = pk.u;
}

// ---------------- bf16 mma GEMM, CTA 128x256, 16 warps of 64x32, BK=32 ------
// EPI: 0 bf16 out | 1 GELU->bf16 | 2 +res fp32 out | 3 +res scatter + fused LN2
#define BM 128
#define BN 256
#define LDTW 20                          // words (u32) per 32-bf16 row (padded)
#define A_WORDS (BM * LDTW)              // 2560
#define B_WORDS (BN * LDTW)              // 5120
#define STAGE_WORDS (A_WORDS + B_WORDS)  // 7680 (30720 B)

template<int EPI>
__global__ __launch_bounds__(512, 1) void mgemm_kernel(
    const __nv_bfloat16* __restrict__ A, const __nv_bfloat16* __restrict__ Bw,
    const float* __restrict__ bias, const float* __restrict__ res,
    void* __restrict__ Cv, __nv_bfloat16* __restrict__ Cln,
    const float* __restrict__ lnw, const float* __restrict__ lnb,
    int Nout, int K)
{
    extern __shared__ uint32_t smw[];
    int tid  = threadIdx.x;
    int wid  = tid >> 5, lane = tid & 31;
    int wm   = wid >> 3, wn = wid & 7;
    int g    = lane >> 2, t4 = lane & 3;
    int m0   = blockIdx.y * BM;
    int n0   = blockIdx.x * BN;
    uint32_t sbase = smem_u32(smw);

    float acc[4][4][4];
    #pragma unroll
    for (int i = 0; i < 4; ++i)
        #pragma unroll
        for (int j = 0; j < 4; ++j)
            #pragma unroll
            for (int k = 0; k < 4; ++k) acc[i][j][k] = 0.0f;

    const int T = K >> 5;

    auto issue = [&](int kt, int s) {
        uint32_t ab = sbase + (uint32_t)(s * STAGE_WORDS) * 4u;
        uint32_t bb = ab + (uint32_t)A_WORDS * 4u;
        int k0 = kt << 5;
        {   // A: 512 chunks of 16B, one per thread
            int row = tid >> 2, cc = tid & 3;
            CP_ASYNC16(ab + (uint32_t)(row * LDTW + cc * 4) * 4u,
                       A + (size_t)(m0 + row) * K + k0 + cc * 8);
        }
        #pragma unroll
        for (int i = 0; i < 2; ++i) {   // B: 1024 chunks
            int c = tid + i * 512;
            int row = c >> 2, cc = c & 3;
            CP_ASYNC16(bb + (uint32_t)(row * LDTW + cc * 4) * 4u,
                       Bw + (size_t)(n0 + row) * K + k0 + cc * 8);
        }
        CP_COMMIT();
    };

    issue(0, 0); issue(1, 1); issue(2, 2);

    int s = 0;
    for (int t = 0; t < T; ++t) {
        CP_WAIT2();
        __syncthreads();
        const uint32_t* As = smw + s * STAGE_WORDS;
        const uint32_t* Bs = As + A_WORDS;

        #pragma unroll
        for (int ks = 0; ks < 2; ++ks) {
            int kw = ks * 8 + t4;
            uint32_t af[4][4], bf2[4][2];
            #pragma unroll
            for (int mt = 0; mt < 4; ++mt) {
                int r = wm * 64 + mt * 16 + g;
                af[mt][0] = As[r * LDTW + kw];
                af[mt][1] = As[(r + 8) * LDTW + kw];
                af[mt][2] = As[r * LDTW + kw + 4];
                af[mt][3] = As[(r + 8) * LDTW + kw + 4];
            }
            #pragma unroll
            for (int nt = 0; nt < 4; ++nt) {
                int n = wn * 32 + nt * 8 + g;
                bf2[nt][0] = Bs[n * LDTW + kw];
                bf2[nt][1] = Bs[n * LDTW + kw + 4];
            }
            #pragma unroll
            for (int mt = 0; mt < 4; ++mt)
                #pragma unroll
                for (int nt = 0; nt < 4; ++nt)
                    mma_bf16(acc[mt][nt], af[mt], bf2[nt]);
        }
        __syncthreads();
        if (t + 3 < T) issue(t + 3, s); else CP_COMMIT();
        if (++s == 3) s = 0;
    }

    const float kS = 0.70710678118654752440f;

    if (EPI == 3) {
        // proj: v = acc + bias + res[pix]; write fp32 C; fused LN2 -> Cln (bf16)
        float* C = (float*)Cv;
        __syncthreads();
        float2* p2      = (float2*)smw;
        float2* rowstat = ((float2*)smw) + 4096;

        #pragma unroll
        for (int mt = 0; mt < 4; ++mt) {
            #pragma unroll
            for (int rr = 0; rr < 2; ++rr) {
                int lm = wm * 64 + mt * 16 + rr * 8 + g;
                int dm = win_to_pix(m0 + lm);
                float*       xrow = C   + (size_t)dm * Nout;
                const float* rrow = res + (size_t)dm * Nout;
                float psum = 0.0f, psq = 0.0f;
                #pragma unroll
                for (int nt = 0; nt < 4; ++nt) {
                    int col = wn * 32 + nt * 8 + t4 * 2;
                    float v0 = acc[mt][nt][rr * 2 + 0] + bias[col]     + rrow[col];
                    float v1 = acc[mt][nt][rr * 2 + 1] + bias[col + 1] + rrow[col + 1];
                    acc[mt][nt][rr * 2 + 0] = v0;
                    acc[mt][nt][rr * 2 + 1] = v1;
                    *(float2*)(xrow + col) = make_float2(v0, v1);
                    psum += v0 + v1; psq += v0 * v0 + v1 * v1;
                }
                p2[tid * 8 + mt * 2 + rr] = make_float2(psum, psq);
            }
        }
        __syncthreads();
        if (tid < 128) {
            int lm = tid;
            int lwm = lm >> 6, lmt = (lm >> 4) & 3, lrr = (lm >> 3) & 1, lg = lm & 7;
            float s1 = 0.0f, s2 = 0.0f;
            #pragma unroll
            for (int w = 0; w < 8; ++w)
                #pragma unroll
                for (int q = 0; q < 4; ++q) {
                    float2 f = p2[(((lwm * 8 + w) << 5) + (lg << 2) + q) * 8 + lmt * 2 + lrr];
                    s1 += f.x; s2 += f.y;
                }
            float mean = s1 * (1.0f / 256.0f);
            float var  = s2 * (1.0f / 256.0f) - mean * mean;
            rowstat[lm] = make_float2(mean, rsqrtf(var + 1e-5f));
        }
        __syncthreads();
        #pragma unroll
        for (int mt = 0; mt < 4; ++mt) {
            #pragma unroll
            for (int rr = 0; rr < 2; ++rr) {
                int lm = wm * 64 + mt * 16 + rr * 8 + g;
                float2 st = rowstat[lm];
                int dm = win_to_pix(m0 + lm);
                __nv_bfloat16* lrow = Cln + (size_t)dm * Nout;
                #pragma unroll
                for (int nt = 0; nt < 4; ++nt) {
                    int col = wn * 32 + nt * 8 + t4 * 2;
                    float v0 = (acc[mt][nt][rr * 2 + 0] - st.x) * st.y * lnw[col]     + lnb[col];
                    float v1 = (acc[mt][nt][rr * 2 + 1] - st.x) * st.y * lnw[col + 1] + lnb[col + 1];
                    *(__nv_bfloat162*)(lrow + col) = __floats2bfloat162_rn(v0, v1);
                }
            }
        }
        return;
    }

    #pragma unroll
    for (int mt = 0; mt < 4; ++mt) {
        #pragma unroll
        for (int rr = 0; rr < 2; ++rr) {
            int m = m0 + wm * 64 + mt * 16 + rr * 8 + g;
            #pragma unroll
            for (int nt = 0; nt < 4; ++nt) {
                int col = wn * 32 + nt * 8 + t4 * 2;
                float v0 = acc[mt][nt][rr * 2 + 0] + bias[n0 + col];
                float v1 = acc[mt][nt][rr * 2 + 1] + bias[n0 + col + 1];
                if (EPI == 1) {
                    v0 = 0.5f * v0 * (1.0f + erff(v0 * kS));
                    v1 = 0.5f * v1 * (1.0f + erff(v1 * kS));
                }
                if (EPI == 2) {
                    const float* rrow = res + (size_t)m * Nout + n0;
                    float* crow = (float*)Cv + (size_t)m * Nout + n0;
                    *(float2*)(crow + col) = make_float2(v0 + rrow[col], v1 + rrow[col + 1]);
                } else {
                    __nv_bfloat16* crow = (__nv_bfloat16*)Cv + (size_t)m * Nout + n0;
                    *(__nv_bfloat162*)(crow + col) = __floats2bfloat162_rn(v0, v1);
                }
            }
        }
    }
}

// ---------------- attention: CTA per (window, head), 128 threads ------------
__global__ __launch_bounds__(128) void attn_kernel(
    const __nv_bfloat16* __restrict__ qkv, const float* __restrict__ rpb,
    const int* __restrict__ rel_idx, const float* __restrict__ mask,
    __nv_bfloat16* __restrict__ out)
{
    __shared__ float sq[NTOK][33];
    __shared__ float sk[NTOK][33];
    __shared__ float sv[NTOK][33];
    __shared__ float S[NTOK][50];

    int blk = blockIdx.x;
    int h   = blk & (HEADS - 1);
    int wv  = blk >> 3;
    int wi  = wv & (NWIN - 1);
    int tid = threadIdx.x;
    int a   = tid >> 4;
    int b   = tid & 15;
    const float scale = 0.17677669529663688f;

    for (int idx = tid; idx < NTOK * HD; idx += 128) {
        int n = idx >> 5, d = idx & 31;
        size_t base = (size_t)(wv * NTOK + n) * 768 + h * HD + d;
        sq[n][d] = __bfloat162float(qkv[base]) * scale;
        sk[n][d] = __bfloat162float(qkv[base + 256]);
        sv[n][d] = __bfloat162float(qkv[base + 512]);
    }
    __syncthreads();

    {
        float acc[7][4];
        #pragma unroll
        for (int i = 0; i < 7; ++i)
            #pragma unroll
            for (int j = 0; j < 4; ++j) acc[i][j] = 0.0f;

        #pragma unroll 8
        for (int d = 0; d < HD; ++d) {
            float qd[7], kd[4];
            #pragma unroll
            for (int i = 0; i < 7; ++i) {
                int n = a + 8 * i;
                qd[i] = (n < NTOK) ? sq[n][d] : 0.0f;
            }
            #pragma unroll
            for (int j = 0; j < 4; ++j) {
                int m = b + 16 * j;
                kd[j] = (m < NTOK) ? sk[m][d] : 0.0f;
            }
            #pragma unroll
            for (int i = 0; i < 7; ++i)
                #pragma unroll
                for (int j = 0; j < 4; ++j) acc[i][j] += qd[i] * kd[j];
        }
        const float* mrow = mask + (size_t)wi * (NTOK * NTOK);
        #pragma unroll
        for (int i = 0; i < 7; ++i) {
            int n = a + 8 * i;
            if (n >= NTOK) break;
            #pragma unroll
            for (int j = 0; j < 4; ++j) {
                int m = b + 16 * j;
                if (m < NTOK) {
                    int e = n * NTOK + m;
                    S[n][m] = acc[i][j] + rpb[rel_idx[e] * HEADS + h] + mrow[e];
                }
            }
        }
    }
    __syncthreads();

    int warp = tid >> 5, lane = tid & 31;
    for (int r = warp; r < NTOK; r += 4) {
        float mx = -1e30f;
        for (int m = lane; m < NTOK; m += 32) mx = fmaxf(mx, S[r][m]);
        #pragma unroll
        for (int o = 16; o; o >>= 1) mx = fmaxf(mx, __shfl_xor_sync(0xffffffffu, mx, o));
        float sum = 0.0f;
        for (int m = lane; m < NTOK; m += 32) {
            float e = __expf(S[r][m] - mx);
            S[r][m] = e;
            sum += e;
        }
        #pragma unroll
        for (int o = 16; o; o >>= 1) sum += __shfl_xor_sync(0xffffffffu, sum, o);
        float inv = 1.0f / sum;
        for (int m = lane; m < NTOK; m += 32) S[r][m] *= inv;
    }
    __syncthreads();

    {
        float o0[7], o1[7];
        #pragma unroll
        for (int i = 0; i < 7; ++i) { o0[i] = 0.0f; o1[i] = 0.0f; }
        int d0 = b * 2;
        for (int m = 0; m < NTOK; ++m) {
            float v0 = sv[m][d0], v1 = sv[m][d0 + 1];
            #pragma unroll
            for (int i = 0; i < 7; ++i) {
                int n = a + 8 * i;
                float sv_ = (n < NTOK) ? S[n][m] : 0.0f;
                o0[i] += sv_ * v0;
                o1[i] += sv_ * v1;
            }
        }
        #pragma unroll
        for (int i = 0; i < 7; ++i) {
            int n = a + 8 * i;
            if (n < NTOK) {
                __nv_bfloat16* orow = out + (size_t)(wv * NTOK + n) * DIM + h * HD + d0;
                *(__nv_bfloat162*)orow = __floats2bfloat162_rn(o0[i], o1[i]);
            }
        }
    }
}

// ---------------- launch --------------------------------------------------
extern "C" void kernel_launch(void* const* d_in, const int* in_sizes, int n_in,
                              void* d_out, int out_size) {
    const float* x     = (const float*)d_in[0];
    const float* n1w   = (const float*)d_in[1];
    const float* n1b   = (const float*)d_in[2];
    const float* qkvw  = (const float*)d_in[3];
    const float* qkvb  = (const float*)d_in[4];
    const float* rpb   = (const float*)d_in[5];
    const float* projw = (const float*)d_in[6];
    const float* projb = (const float*)d_in[7];
    const float* n2w   = (const float*)d_in[8];
    const float* n2b   = (const float*)d_in[9];
    const float* fc1w  = (const float*)d_in[10];
    const float* fc1b  = (const float*)d_in[11];
    const float* fc2w  = (const float*)d_in[12];
    const float* fc2b  = (const float*)d_in[13];
    const int*   relix = (const int*)d_in[14];
    const float* mask  = (const float*)d_in[15];
    float* out = (float*)d_out;

    __nv_bfloat16 *bufA, *bufB, *bufC, *bufW;
    float *bufX;
    cudaGetSymbolAddress((void**)&bufA, g_bufA);
    cudaGetSymbolAddress((void**)&bufB, g_bufB);
    cudaGetSymbolAddress((void**)&bufC, g_bufC);
    cudaGetSymbolAddress((void**)&bufX, g_bufX);
    cudaGetSymbolAddress((void**)&bufW, g_bufW);

    __nv_bfloat16* wqkv = bufW;
    __nv_bfloat16* wprj = wqkv + 196608;
    __nv_bfloat16* wfc1 = wprj + 65536;
    __nv_bfloat16* wfc2 = wfc1 + 262144;

    const int LN_BLOCKS = T_TOK / 8;
    const int MT = T_TOK / BM;              // 784
    const int SHMEM = 3 * STAGE_WORDS * 4;  // 92160

    cudaFuncSetAttribute(mgemm_kernel<0>, cudaFuncAttributeMaxDynamicSharedMemorySize, SHMEM);
    cudaFuncSetAttribute(mgemm_kernel<1>, cudaFuncAttributeMaxDynamicSharedMemorySize, SHMEM);
    cudaFuncSetAttribute(mgemm_kernel<2>, cudaFuncAttributeMaxDynamicSharedMemorySize, SHMEM);
    cudaFuncSetAttribute(mgemm_kernel<3>, cudaFuncAttributeMaxDynamicSharedMemorySize, SHMEM);

    // 0) convert weights to bf16
    convw_kernel<<<(196608 + 255) / 256, 256>>>(qkvw, wqkv, 196608);
    convw_kernel<<<(65536  + 255) / 256, 256>>>(projw, wprj, 65536);
    convw_kernel<<<(262144 + 255) / 256, 256>>>(fc1w, wfc1, 262144);
    convw_kernel<<<(262144 + 255) / 256, 256>>>(fc2w, wfc2, 262144);

    // 1) LN1 + shift + window partition -> bufB (bf16)
    ln_kernel<<<LN_BLOCKS, 256>>>(x, n1w, n1b, bufB);

    // 2) qkv GEMM -> bufA [T,768] (bf16)
    mgemm_kernel<0><<<dim3(768 / BN, MT), 512, SHMEM>>>(
        bufB, wqkv, qkvb, nullptr, bufA, nullptr, nullptr, nullptr, 768, DIM);

    // 3) attention -> bufB (bf16, window order)
    attn_kernel<<<(T_TOK / NTOK) * HEADS, 128>>>(bufA, rpb, relix, mask, bufB);

    // 4) proj + scatter + residual + fused LN2 -> bufX (fp32), bufC (bf16)
    mgemm_kernel<3><<<dim3(1, MT), 512, SHMEM>>>(
        bufB, wprj, projb, x, bufX, bufC, n2w, n2b, DIM, DIM);

    // 5) fc1 + GELU -> bufA [T,1024] (bf16)
    mgemm_kernel<1><<<dim3(HIDDEN / BN, MT), 512, SHMEM>>>(
        bufC, wfc1, fc1b, nullptr, bufA, nullptr, nullptr, nullptr, HIDDEN, DIM);

    // 6) fc2 + residual -> d_out (fp32)
    mgemm_kernel<2><<<dim3(1, MT), 512, SHMEM>>>(
        bufA, wfc2, fc2b, bufX, out, nullptr, nullptr, nullptr, DIM, HIDDEN);
}

// round 6
// speedup vs baseline: 4.7678x; 1.0720x over previous
#include <cuda_runtime.h>
#include <cuda_bf16.h>
#include <cstdint>
#include <math.h>

// ---------------- problem constants ----------------
#define BATCH   32
#define HH      56
#define WIMG    56
#define DIM     256
#define HEADS   8
#define HD      32
#define WS      7
#define SHIFT   3
#define NTOK    49
#define NWIN    64
#define HIDDEN  1024
#define T_TOK   100352

// ---------------- scratch ----------------
__device__ __nv_bfloat16 g_bufA[(size_t)T_TOK * 1024]; // qkv [T,768] / fc1-out [T,1024]
__device__ __nv_bfloat16 g_bufB[(size_t)T_TOK * 256];  // LN1-out / attn-out
__device__ __nv_bfloat16 g_bufC[(size_t)T_TOK * 256];  // LN2-out
__device__ float         g_bufX[(size_t)T_TOK * 256];  // x after first residual (fp32)
__device__ __nv_bfloat16 g_bufW[786432];               // bf16 weights: qkv|proj|fc1|fc2

// ---------------- helpers ----------------
__device__ __forceinline__ uint32_t smem_u32(const void* p) {
    uint32_t a;
    asm("{ .reg .u64 t; cvta.to.shared.u64 t, %1; cvt.u32.u64 %0, t; }" : "=r"(a) : "l"(p));
    return a;
}
#define CP_ASYNC16(dst, src) \
    asm volatile("cp.async.cg.shared.global [%0], [%1], 16;\n" :: "r"(dst), "l"(src))
#define CP_COMMIT() asm volatile("cp.async.commit_group;\n" ::: "memory")
#define CP_WAIT2()  asm volatile("cp.async.wait_group 2;\n" ::: "memory")

__device__ __forceinline__ void mma_bf16(float* d, const uint32_t* a, const uint32_t* b) {
    asm volatile(
        "mma.sync.aligned.m16n8k16.row.col.f32.bf16.bf16.f32 "
        "{%0,%1,%2,%3}, {%4,%5,%6,%7}, {%8,%9}, {%0,%1,%2,%3};"
        : "+f"(d[0]), "+f"(d[1]), "+f"(d[2]), "+f"(d[3])
        : "r"(a[0]), "r"(a[1]), "r"(a[2]), "r"(a[3]), "r"(b[0]), "r"(b[1]));
}

__device__ __forceinline__ int win_to_pix(int m) {
    int n_in = m % NTOK;
    int wv   = m / NTOK;
    int bimg = wv >> 6;
    int wi   = wv & 63;
    int wh   = wi >> 3;
    int wc   = wi & 7;
    int i    = n_in / WS;
    int j    = n_in - i * WS;
    int pr   = wh * WS + i + SHIFT; if (pr >= HH)   pr -= HH;
    int pc   = wc * WS + j + SHIFT; if (pc >= WIMG) pc -= WIMG;
    return bimg * (HH * WIMG) + pr * WIMG + pc;
}

// ---------------- all weights -> bf16, one kernel ----------------
__global__ void convw_kernel(const float* __restrict__ s0, const float* __restrict__ s1,
                             const float* __restrict__ s2, const float* __restrict__ s3,
                             __nv_bfloat16* __restrict__ d) {
    int i = blockIdx.x * 256 + threadIdx.x;
    if (i >= 786432) return;
    float v;
    if (i < 196608)      v = s0[i];
    else if (i < 262144) v = s1[i - 196608];
    else if (i < 524288) v = s2[i - 262144];
    else                 v = s3[i - 524288];
    d[i] = __float2bfloat16_rn(v);
}

// ---------------- LayerNorm + shift + window gather, bf16 output ------------
__global__ __launch_bounds__(256) void ln_kernel(
    const float* __restrict__ x, const float* __restrict__ w,
    const float* __restrict__ b, __nv_bfloat16* __restrict__ out)
{
    int t    = blockIdx.x * 8 + (threadIdx.x >> 5);
    int lane = threadIdx.x & 31;
    int src  = win_to_pix(t);

    const float4* px = (const float4*)(x + (size_t)src * DIM) + lane * 2;
    float4 v0 = px[0], v1 = px[1];

    float s  = v0.x + v0.y + v0.z + v0.w + v1.x + v1.y + v1.z + v1.w;
    float ss = v0.x*v0.x + v0.y*v0.y + v0.z*v0.z + v0.w*v0.w
             + v1.x*v1.x + v1.y*v1.y + v1.z*v1.z + v1.w*v1.w;
    #pragma unroll
    for (int o = 16; o; o >>= 1) {
        s  += __shfl_xor_sync(0xffffffffu, s,  o);
        ss += __shfl_xor_sync(0xffffffffu, ss, o);
    }
    float mean = s * (1.0f / DIM);
    float var  = ss * (1.0f / DIM) - mean * mean;
    float rstd = rsqrtf(var + 1e-5f);

    int c0 = lane * 8;
    const float4* pw = (const float4*)(w + c0);
    const float4* pb = (const float4*)(b + c0);
    float4 w0 = pw[0], w1 = pw[1], b0 = pb[0], b1 = pb[1];

    union { __nv_bfloat162 h2[4]; uint4 u; } pk;
    pk.h2[0] = __floats2bfloat162_rn((v0.x - mean) * rstd * w0.x + b0.x,
                                     (v0.y - mean) * rstd * w0.y + b0.y);
    pk.h2[1] = __floats2bfloat162_rn((v0.z - mean) * rstd * w0.z + b0.z,
                                     (v0.w - mean) * rstd * w0.w + b0.w);
    pk.h2[2] = __floats2bfloat162_rn((v1.x - mean) * rstd * w1.x + b1.x,
                                     (v1.y - mean) * rstd * w1.y + b1.y);
    pk.h2[3] = __floats2bfloat162_rn((v1.z - mean) * rstd * w1.z + b1.z,
                                     (v1.w - mean) * rstd * w1.w + b1.w);
    *(uint4*)(out + (size_t)t * DIM + c0) = pk.u;
}

#define LDTW 20   // u32 words per 32-bf16 row (padded)

// ============ 256-thread GEMM, CTA 128x128, 8 warps of 64x32, BK=32 =========
// EPI: 0 bf16 out | 1 GELU->bf16 | 2 +res fp32 out
#define A_W2 (128 * LDTW)
#define STG2 (2 * A_W2)                  // 5120 words / stage

template<int EPI>
__global__ __launch_bounds__(256, 2) void mgemm2_kernel(
    const __nv_bfloat16* __restrict__ A, const __nv_bfloat16* __restrict__ Bw,
    const float* __restrict__ bias, const float* __restrict__ res,
    void* __restrict__ Cv, int Nout, int K)
{
    extern __shared__ uint32_t smw[];
    int tid  = threadIdx.x;
    int wid  = tid >> 5, lane = tid & 31;
    int wm   = wid >> 2, wn = wid & 3;
    int g    = lane >> 2, t4 = lane & 3;
    int m0   = blockIdx.y * 128;
    int n0   = blockIdx.x * 128;
    uint32_t sbase = smem_u32(smw);

    float acc[4][4][4];
    #pragma unroll
    for (int i = 0; i < 4; ++i)
        #pragma unroll
        for (int j = 0; j < 4; ++j)
            #pragma unroll
            for (int k = 0; k < 4; ++k) acc[i][j][k] = 0.0f;

    const int T = K >> 5;

    auto issue = [&](int kt, int s) {
        uint32_t ab = sbase + (uint32_t)(s * STG2) * 4u;
        uint32_t bb = ab + (uint32_t)A_W2 * 4u;
        int k0 = kt << 5;
        #pragma unroll
        for (int i = 0; i < 2; ++i) {
            int c = tid + i * 256;
            int row = c >> 2, cc = c & 3;
            CP_ASYNC16(ab + (uint32_t)(row * LDTW + cc * 4) * 4u,
                       A + (size_t)(m0 + row) * K + k0 + cc * 8);
        }
        #pragma unroll
        for (int i = 0; i < 2; ++i) {
            int c = tid + i * 256;
            int row = c >> 2, cc = c & 3;
            CP_ASYNC16(bb + (uint32_t)(row * LDTW + cc * 4) * 4u,
                       Bw + (size_t)(n0 + row) * K + k0 + cc * 8);
        }
        CP_COMMIT();
    };

    issue(0, 0); issue(1, 1); issue(2, 2);

    int s = 0;
    for (int t = 0; t < T; ++t) {
        CP_WAIT2();
        __syncthreads();
        const uint32_t* As = smw + s * STG2;
        const uint32_t* Bs = As + A_W2;

        #pragma unroll
        for (int ks = 0; ks < 2; ++ks) {
            int kw = ks * 8 + t4;
            uint32_t af[4][4], bf2[4][2];
            #pragma unroll
            for (int mt = 0; mt < 4; ++mt) {
                int r = wm * 64 + mt * 16 + g;
                af[mt][0] = As[r * LDTW + kw];
                af[mt][1] = As[(r + 8) * LDTW + kw];
                af[mt][2] = As[r * LDTW + kw + 4];
                af[mt][3] = As[(r + 8) * LDTW + kw + 4];
            }
            #pragma unroll
            for (int nt = 0; nt < 4; ++nt) {
                int n = wn * 32 + nt * 8 + g;
                bf2[nt][0] = Bs[n * LDTW + kw];
                bf2[nt][1] = Bs[n * LDTW + kw + 4];
            }
            #pragma unroll
            for (int mt = 0; mt < 4; ++mt)
                #pragma unroll
                for (int nt = 0; nt < 4; ++nt)
                    mma_bf16(acc[mt][nt], af[mt], bf2[nt]);
        }
        __syncthreads();
        if (t + 3 < T) issue(t + 3, s); else CP_COMMIT();
        if (++s == 3) s = 0;
    }

    const float kS = 0.70710678118654752440f;
    #pragma unroll
    for (int mt = 0; mt < 4; ++mt) {
        #pragma unroll
        for (int rr = 0; rr < 2; ++rr) {
            int m = m0 + wm * 64 + mt * 16 + rr * 8 + g;
            #pragma unroll
            for (int nt = 0; nt < 4; ++nt) {
                int col = wn * 32 + nt * 8 + t4 * 2;
                float v0 = acc[mt][nt][rr * 2 + 0] + bias[n0 + col];
                float v1 = acc[mt][nt][rr * 2 + 1] + bias[n0 + col + 1];
                if (EPI == 1) {
                    v0 = 0.5f * v0 * (1.0f + erff(v0 * kS));
                    v1 = 0.5f * v1 * (1.0f + erff(v1 * kS));
                }
                if (EPI == 2) {
                    const float* rrow = res + (size_t)m * Nout + n0;
                    float* crow = (float*)Cv + (size_t)m * Nout + n0;
                    *(float2*)(crow + col) = make_float2(v0 + rrow[col], v1 + rrow[col + 1]);
                } else {
                    __nv_bfloat16* crow = (__nv_bfloat16*)Cv + (size_t)m * Nout + n0;
                    *(__nv_bfloat162*)(crow + col) = __floats2bfloat162_rn(v0, v1);
                }
            }
        }
    }
}

// ===== 512-thread proj GEMM, CTA 128x256: +bias+res scatter + fused LN2 =====
#define A_WORDS (128 * LDTW)
#define B_WORDS (256 * LDTW)
#define STAGE_WORDS (A_WORDS + B_WORDS)

__global__ __launch_bounds__(512, 1) void proj_kernel(
    const __nv_bfloat16* __restrict__ A, const __nv_bfloat16* __restrict__ Bw,
    const float* __restrict__ bias, const float* __restrict__ res,
    float* __restrict__ C, __nv_bfloat16* __restrict__ Cln,
    const float* __restrict__ lnw, const float* __restrict__ lnb)
{
    const int Nout = 256, K = 256;
    extern __shared__ uint32_t smw[];
    int tid  = threadIdx.x;
    int wid  = tid >> 5, lane = tid & 31;
    int wm   = wid >> 3, wn = wid & 7;
    int g    = lane >> 2, t4 = lane & 3;
    int m0   = blockIdx.y * 128;
    uint32_t sbase = smem_u32(smw);

    float acc[4][4][4];
    #pragma unroll
    for (int i = 0; i < 4; ++i)
        #pragma unroll
        for (int j = 0; j < 4; ++j)
            #pragma unroll
            for (int k = 0; k < 4; ++k) acc[i][j][k] = 0.0f;

    const int T = K >> 5;   // 8

    auto issue = [&](int kt, int s) {
        uint32_t ab = sbase + (uint32_t)(s * STAGE_WORDS) * 4u;
        uint32_t bb = ab + (uint32_t)A_WORDS * 4u;
        int k0 = kt << 5;
        {
            int row = tid >> 2, cc = tid & 3;
            CP_ASYNC16(ab + (uint32_t)(row * LDTW + cc * 4) * 4u,
                       A + (size_t)(m0 + row) * K + k0 + cc * 8);
        }
        #pragma unroll
        for (int i = 0; i < 2; ++i) {
            int c = tid + i * 512;
            int row = c >> 2, cc = c & 3;
            CP_ASYNC16(bb + (uint32_t)(row * LDTW + cc * 4) * 4u,
                       Bw + (size_t)row * K + k0 + cc * 8);
        }
        CP_COMMIT();
    };

    issue(0, 0); issue(1, 1); issue(2, 2);

    int s = 0;
    for (int t = 0; t < T; ++t) {
        CP_WAIT2();
        __syncthreads();
        const uint32_t* As = smw + s * STAGE_WORDS;
        const uint32_t* Bs = As + A_WORDS;

        #pragma unroll
        for (int ks = 0; ks < 2; ++ks) {
            int kw = ks * 8 + t4;
            uint32_t af[4][4], bf2[4][2];
            #pragma unroll
            for (int mt = 0; mt < 4; ++mt) {
                int r = wm * 64 + mt * 16 + g;
                af[mt][0] = As[r * LDTW + kw];
                af[mt][1] = As[(r + 8) * LDTW + kw];
                af[mt][2] = As[r * LDTW + kw + 4];
                af[mt][3] = As[(r + 8) * LDTW + kw + 4];
            }
            #pragma unroll
            for (int nt = 0; nt < 4; ++nt) {
                int n = wn * 32 + nt * 8 + g;
                bf2[nt][0] = Bs[n * LDTW + kw];
                bf2[nt][1] = Bs[n * LDTW + kw + 4];
            }
            #pragma unroll
            for (int mt = 0; mt < 4; ++mt)
                #pragma unroll
                for (int nt = 0; nt < 4; ++nt)
                    mma_bf16(acc[mt][nt], af[mt], bf2[nt]);
        }
        __syncthreads();
        if (t + 3 < T) issue(t + 3, s); else CP_COMMIT();
        if (++s == 3) s = 0;
    }

    __syncthreads();
    float2* p2      = (float2*)smw;
    float2* rowstat = ((float2*)smw) + 4096;

    #pragma unroll
    for (int mt = 0; mt < 4; ++mt) {
        #pragma unroll
        for (int rr = 0; rr < 2; ++rr) {
            int lm = wm * 64 + mt * 16 + rr * 8 + g;
            int dm = win_to_pix(m0 + lm);
            float*       xrow = C   + (size_t)dm * Nout;
            const float* rrow = res + (size_t)dm * Nout;
            float psum = 0.0f, psq = 0.0f;
            #pragma unroll
            for (int nt = 0; nt < 4; ++nt) {
                int col = wn * 32 + nt * 8 + t4 * 2;
                float v0 = acc[mt][nt][rr * 2 + 0] + bias[col]     + rrow[col];
                float v1 = acc[mt][nt][rr * 2 + 1] + bias[col + 1] + rrow[col + 1];
                acc[mt][nt][rr * 2 + 0] = v0;
                acc[mt][nt][rr * 2 + 1] = v1;
                *(float2*)(xrow + col) = make_float2(v0, v1);
                psum += v0 + v1; psq += v0 * v0 + v1 * v1;
            }
            p2[tid * 8 + mt * 2 + rr] = make_float2(psum, psq);
        }
    }
    __syncthreads();
    if (tid < 128) {
        int lm = tid;
        int lwm = lm >> 6, lmt = (lm >> 4) & 3, lrr = (lm >> 3) & 1, lg = lm & 7;
        float s1 = 0.0f, s2 = 0.0f;
        #pragma unroll
        for (int w = 0; w < 8; ++w)
            #pragma unroll
            for (int q = 0; q < 4; ++q) {
                float2 f = p2[(((lwm * 8 + w) << 5) + (lg << 2) + q) * 8 + lmt * 2 + lrr];
                s1 += f.x; s2 += f.y;
            }
        float mean = s1 * (1.0f / 256.0f);
        float var  = s2 * (1.0f / 256.0f) - mean * mean;
        rowstat[lm] = make_float2(mean, rsqrtf(var + 1e-5f));
    }
    __syncthreads();
    #pragma unroll
    for (int mt = 0; mt < 4; ++mt) {
        #pragma unroll
        for (int rr = 0; rr < 2; ++rr) {
            int lm = wm * 64 + mt * 16 + rr * 8 + g;
            float2 st = rowstat[lm];
            int dm = win_to_pix(m0 + lm);
            __nv_bfloat16* lrow = Cln + (size_t)dm * Nout;
            #pragma unroll
            for (int nt = 0; nt < 4; ++nt) {
                int col = wn * 32 + nt * 8 + t4 * 2;
                float v0 = (acc[mt][nt][rr * 2 + 0] - st.x) * st.y * lnw[col]     + lnb[col];
                float v1 = (acc[mt][nt][rr * 2 + 1] - st.x) * st.y * lnw[col + 1] + lnb[col + 1];
                *(__nv_bfloat162*)(lrow + col) = __floats2bfloat162_rn(v0, v1);
            }
        }
    }
}

// ---------------- attention: CTA per (window, head), 128 threads ------------
__global__ __launch_bounds__(128) void attn_kernel(
    const __nv_bfloat16* __restrict__ qkv, const float* __restrict__ rpb,
    const int* __restrict__ rel_idx, const float* __restrict__ mask,
    __nv_bfloat16* __restrict__ out)
{
    __shared__ float sq[56][36];
    __shared__ float sk[64][36];
    __shared__ float sv[52][36];
    __shared__ float S[56][52];

    int blk = blockIdx.x;
    int h   = blk & (HEADS - 1);
    int wv  = blk >> 3;
    int wi  = wv & (NWIN - 1);
    int tid = threadIdx.x;
    int a   = tid >> 4;      // 0..7
    int b   = tid & 15;      // 0..15
    const float scale = 0.17677669529663688f;

    // zero-fill (padding rows/cols must be 0)
    {
        float* z = (float*)sq;
        for (int i = tid; i < 56*36 + 64*36 + 52*36; i += 128) z[i] = 0.0f;
        for (int i = tid; i < 56*52; i += 128) ((float*)S)[i] = 0.0f;
    }
    __syncthreads();

    for (int idx = tid; idx < NTOK * HD; idx += 128) {
        int n = idx >> 5, d = idx & 31;
        size_t base = (size_t)(wv * NTOK + n) * 768 + h * HD + d;
        sq[n][d] = __bfloat162float(qkv[base]) * scale;
        sk[n][d] = __bfloat162float(qkv[base + 256]);
        sv[n][d] = __bfloat162float(qkv[base + 512]);
    }
    __syncthreads();

    // S = q k^T, 7x4 per thread, float4 over d
    {
        float acc[7][4];
        #pragma unroll
        for (int i = 0; i < 7; ++i)
            #pragma unroll
            for (int j = 0; j < 4; ++j) acc[i][j] = 0.0f;

        #pragma unroll
        for (int dd = 0; dd < 8; ++dd) {
            float4 qd[7], kd[4];
            #pragma unroll
            for (int i = 0; i < 7; ++i) qd[i] = *(const float4*)&sq[a + 8 * i][dd * 4];
            #pragma unroll
            for (int j = 0; j < 4; ++j) kd[j] = *(const float4*)&sk[b + 16 * j][dd * 4];
            #pragma unroll
            for (int i = 0; i < 7; ++i)
                #pragma unroll
                for (int j = 0; j < 4; ++j) {
                    acc[i][j] += qd[i].x * kd[j].x + qd[i].y * kd[j].y
                               + qd[i].z * kd[j].z + qd[i].w * kd[j].w;
                }
        }
        const float* mrow = mask + (size_t)wi * (NTOK * NTOK);
        #pragma unroll
        for (int i = 0; i < 7; ++i) {
            int n = a + 8 * i;
            if (n >= NTOK) break;
            #pragma unroll
            for (int j = 0; j < 4; ++j) {
                int m = b + 16 * j;
                if (m < NTOK) {
                    int e = n * NTOK + m;
                    S[n][m] = acc[i][j] + rpb[rel_idx[e] * HEADS + h] + mrow[e];
                }
            }
        }
    }
    __syncthreads();

    // softmax: warp per row (padding cols stay 0)
    int warp = tid >> 5, lane = tid & 31;
    for (int r = warp; r < NTOK; r += 4) {
        float mx = -1e30f;
        for (int m = lane; m < NTOK; m += 32) mx = fmaxf(mx, S[r][m]);
        #pragma unroll
        for (int o = 16; o; o >>= 1) mx = fmaxf(mx, __shfl_xor_sync(0xffffffffu, mx, o));
        float sum = 0.0f;
        for (int m = lane; m < NTOK; m += 32) {
            float e = __expf(S[r][m] - mx);
            S[r][m] = e;
            sum += e;
        }
        #pragma unroll
        for (int o = 16; o; o >>= 1) sum += __shfl_xor_sync(0xffffffffu, sum, o);
        float inv = 1.0f / sum;
        for (int m = lane; m < NTOK; m += 32) S[r][m] *= inv;
    }
    __syncthreads();

    // out = S @ V, 7 rows x 2 cols, m vectorized by 4
    {
        float o0[7], o1[7];
        #pragma unroll
        for (int i = 0; i < 7; ++i) { o0[i] = 0.0f; o1[i] = 0.0f; }
        int d0 = b * 2;
        #pragma unroll
        for (int mc = 0; mc < 13; ++mc) {
            int m = mc * 4;
            float2 v0 = *(const float2*)&sv[m + 0][d0];
            float2 v1 = *(const float2*)&sv[m + 1][d0];
            float2 v2 = *(const float2*)&sv[m + 2][d0];
            float2 v3 = *(const float2*)&sv[m + 3][d0];
            #pragma unroll
            for (int i = 0; i < 7; ++i) {
                float4 s4 = *(const float4*)&S[a + 8 * i][m];
                o0[i] += s4.x * v0.x + s4.y * v1.x + s4.z * v2.x + s4.w * v3.x;
                o1[i] += s4.x * v0.y + s4.y * v1.y + s4.z * v2.y + s4.w * v3.y;
            }
        }
        #pragma unroll
        for (int i = 0; i < 7; ++i) {
            int n = a + 8 * i;
            if (n < NTOK) {
                __nv_bfloat16* orow = out + (size_t)(wv * NTOK + n) * DIM + h * HD + d0;
                *(__nv_bfloat162*)orow = __floats2bfloat162_rn(o0[i], o1[i]);
            }
        }
    }
}

// ---------------- launch --------------------------------------------------
extern "C" void kernel_launch(void* const* d_in, const int* in_sizes, int n_in,
                              void* d_out, int out_size) {
    const float* x     = (const float*)d_in[0];
    const float* n1w   = (const float*)d_in[1];
    const float* n1b   = (const float*)d_in[2];
    const float* qkvw  = (const float*)d_in[3];
    const float* qkvb  = (const float*)d_in[4];
    const float* rpb   = (const float*)d_in[5];
    const float* projw = (const float*)d_in[6];
    const float* projb = (const float*)d_in[7];
    const float* n2w   = (const float*)d_in[8];
    const float* n2b   = (const float*)d_in[9];
    const float* fc1w  = (const float*)d_in[10];
    const float* fc1b  = (const float*)d_in[11];
    const float* fc2w  = (const float*)d_in[12];
    const float* fc2b  = (const float*)d_in[13];
    const int*   relix = (const int*)d_in[14];
    const float* mask  = (const float*)d_in[15];
    float* out = (float*)d_out;

    __nv_bfloat16 *bufA, *bufB, *bufC, *bufW;
    float *bufX;
    cudaGetSymbolAddress((void**)&bufA, g_bufA);
    cudaGetSymbolAddress((void**)&bufB, g_bufB);
    cudaGetSymbolAddress((void**)&bufC, g_bufC);
    cudaGetSymbolAddress((void**)&bufX, g_bufX);
    cudaGetSymbolAddress((void**)&bufW, g_bufW);

    __nv_bfloat16* wqkv = bufW;
    __nv_bfloat16* wprj = wqkv + 196608;
    __nv_bfloat16* wfc1 = wprj + 65536;
    __nv_bfloat16* wfc2 = wfc1 + 262144;

    const int LN_BLOCKS = T_TOK / 8;
    const int MT = T_TOK / 128;             // 784
    const int SH2  = 3 * STG2 * 4;          // 61440
    const int SHP  = 3 * STAGE_WORDS * 4;   // 92160

    cudaFuncSetAttribute(mgemm2_kernel<0>, cudaFuncAttributeMaxDynamicSharedMemorySize, SH2);
    cudaFuncSetAttribute(mgemm2_kernel<1>, cudaFuncAttributeMaxDynamicSharedMemorySize, SH2);
    cudaFuncSetAttribute(mgemm2_kernel<2>, cudaFuncAttributeMaxDynamicSharedMemorySize, SH2);
    cudaFuncSetAttribute(proj_kernel, cudaFuncAttributeMaxDynamicSharedMemorySize, SHP);

    // 0) convert weights to bf16 (single kernel)
    convw_kernel<<<(786432 + 255) / 256, 256>>>(qkvw, projw, fc1w, fc2w, bufW);

    // 1) LN1 + shift + window partition -> bufB (bf16)
    ln_kernel<<<LN_BLOCKS, 256>>>(x, n1w, n1b, bufB);

    // 2) qkv GEMM -> bufA [T,768] (bf16)
    mgemm2_kernel<0><<<dim3(768 / 128, MT), 256, SH2>>>(
        bufB, wqkv, qkvb, nullptr, bufA, 768, DIM);

    // 3) attention -> bufB (bf16, window order)
    attn_kernel<<<(T_TOK / NTOK) * HEADS, 128>>>(bufA, rpb, relix, mask, bufB);

    // 4) proj + scatter + residual + fused LN2 -> bufX (fp32), bufC (bf16)
    proj_kernel<<<dim3(1, MT), 512, SHP>>>(
        bufB, wprj, projb, x, bufX, bufC, n2w, n2b);

    // 5) fc1 + GELU -> bufA [T,1024] (bf16)
    mgemm2_kernel<1><<<dim3(HIDDEN / 128, MT), 256, SH2>>>(
        bufC, wfc1, fc1b, nullptr, bufA, HIDDEN, DIM);

    // 6) fc2 + residual -> d_out (fp32)
    mgemm2_kernel<2><<<dim3(DIM / 128, MT), 256, SH2>>>(
        bufA, wfc2, fc2b, bufX, out, DIM, HIDDEN);
}

// round 7
// speedup vs baseline: 6.0731x; 1.2738x over previous
#include <cuda_runtime.h>
#include <cuda_bf16.h>
#include <cstdint>
#include <math.h>

// ---------------- problem constants ----------------
#define BATCH   32
#define HH      56
#define WIMG    56
#define DIM     256
#define HEADS   8
#define HD      32
#define WS      7
#define SHIFT   3
#define NTOK    49
#define NWIN    64
#define HIDDEN  1024
#define T_TOK   100352

// ---------------- scratch ----------------
__device__ __nv_bfloat16 g_bufA[(size_t)T_TOK * 1024]; // qkv [T,768] / fc1-out [T,1024]
__device__ __nv_bfloat16 g_bufB[(size_t)T_TOK * 256];  // LN1-out / attn-out
__device__ __nv_bfloat16 g_bufC[(size_t)T_TOK * 256];  // LN2-out
__device__ float         g_bufX[(size_t)T_TOK * 256];  // x after first residual (fp32)
__device__ __nv_bfloat16 g_bufW[786432];               // bf16 weights: qkv|proj|fc1|fc2
__device__ float         g_comb[NWIN * HEADS * NTOK * NTOK]; // rpb-gather + mask

// ---------------- helpers ----------------
__device__ __forceinline__ uint32_t smem_u32(const void* p) {
    uint32_t a;
    asm("{ .reg .u64 t; cvta.to.shared.u64 t, %1; cvt.u32.u64 %0, t; }" : "=r"(a) : "l"(p));
    return a;
}
#define CP_ASYNC16(dst, src) \
    asm volatile("cp.async.cg.shared.global [%0], [%1], 16;\n" :: "r"(dst), "l"(src))
#define CP_COMMIT() asm volatile("cp.async.commit_group;\n" ::: "memory")
#define CP_WAIT2()  asm volatile("cp.async.wait_group 2;\n" ::: "memory")

__device__ __forceinline__ void mma_bf16(float* d, const uint32_t* a, const uint32_t* b) {
    asm volatile(
        "mma.sync.aligned.m16n8k16.row.col.f32.bf16.bf16.f32 "
        "{%0,%1,%2,%3}, {%4,%5,%6,%7}, {%8,%9}, {%0,%1,%2,%3};"
        : "+f"(d[0]), "+f"(d[1]), "+f"(d[2]), "+f"(d[3])
        : "r"(a[0]), "r"(a[1]), "r"(a[2]), "r"(a[3]), "r"(b[0]), "r"(b[1]));
}

__device__ __forceinline__ uint32_t packbf(float x, float y) {
    __nv_bfloat162 h = __floats2bfloat162_rn(x, y);
    return *(uint32_t*)&h;
}

__device__ __forceinline__ int win_to_pix(int m) {
    int n_in = m % NTOK;
    int wv   = m / NTOK;
    int bimg = wv >> 6;
    int wi   = wv & 63;
    int wh   = wi >> 3;
    int wc   = wi & 7;
    int i    = n_in / WS;
    int j    = n_in - i * WS;
    int pr   = wh * WS + i + SHIFT; if (pr >= HH)   pr -= HH;
    int pc   = wc * WS + j + SHIFT; if (pc >= WIMG) pc -= WIMG;
    return bimg * (HH * WIMG) + pr * WIMG + pc;
}

// ---------------- all weights -> bf16, one kernel ----------------
__global__ void convw_kernel(const float* __restrict__ s0, const float* __restrict__ s1,
                             const float* __restrict__ s2, const float* __restrict__ s3,
                             __nv_bfloat16* __restrict__ d) {
    int i = blockIdx.x * 256 + threadIdx.x;
    if (i >= 786432) return;
    float v;
    if (i < 196608)      v = s0[i];
    else if (i < 262144) v = s1[i - 196608];
    else if (i < 524288) v = s2[i - 262144];
    else                 v = s3[i - 524288];
    d[i] = __float2bfloat16_rn(v);
}

// ---------------- combined bias table: comb[wi][h][n][m] --------------------
__global__ void comb_kernel(const float* __restrict__ rpb, const int* __restrict__ relix,
                            const float* __restrict__ mask, float* __restrict__ comb) {
    int wh = blockIdx.x;            // wi*8 + h
    int wi = wh >> 3, h = wh & 7;
    for (int e = threadIdx.x; e < NTOK * NTOK; e += 256)
        comb[(size_t)wh * (NTOK * NTOK) + e] =
            rpb[relix[e] * HEADS + h] + mask[(size_t)wi * (NTOK * NTOK) + e];
}

// ---------------- LayerNorm + shift + window gather, bf16 output ------------
__global__ __launch_bounds__(256) void ln_kernel(
    const float* __restrict__ x, const float* __restrict__ w,
    const float* __restrict__ b, __nv_bfloat16* __restrict__ out)
{
    int t    = blockIdx.x * 8 + (threadIdx.x >> 5);
    int lane = threadIdx.x & 31;
    int src  = win_to_pix(t);

    const float4* px = (const float4*)(x + (size_t)src * DIM) + lane * 2;
    float4 v0 = px[0], v1 = px[1];

    float s  = v0.x + v0.y + v0.z + v0.w + v1.x + v1.y + v1.z + v1.w;
    float ss = v0.x*v0.x + v0.y*v0.y + v0.z*v0.z + v0.w*v0.w
             + v1.x*v1.x + v1.y*v1.y + v1.z*v1.z + v1.w*v1.w;
    #pragma unroll
    for (int o = 16; o; o >>= 1) {
        s  += __shfl_xor_sync(0xffffffffu, s,  o);
        ss += __shfl_xor_sync(0xffffffffu, ss, o);
    }
    float mean = s * (1.0f / DIM);
    float var  = ss * (1.0f / DIM) - mean * mean;
    float rstd = rsqrtf(var + 1e-5f);

    int c0 = lane * 8;
    const float4* pw = (const float4*)(w + c0);
    const float4* pb = (const float4*)(b + c0);
    float4 w0 = pw[0], w1 = pw[1], b0 = pb[0], b1 = pb[1];

    union { __nv_bfloat162 h2[4]; uint4 u; } pk;
    pk.h2[0] = __floats2bfloat162_rn((v0.x - mean) * rstd * w0.x + b0.x,
                                     (v0.y - mean) * rstd * w0.y + b0.y);
    pk.h2[1] = __floats2bfloat162_rn((v0.z - mean) * rstd * w0.z + b0.z,
                                     (v0.w - mean) * rstd * w0.w + b0.w);
    pk.h2[2] = __floats2bfloat162_rn((v1.x - mean) * rstd * w1.x + b1.x,
                                     (v1.y - mean) * rstd * w1.y + b1.y);
    pk.h2[3] = __floats2bfloat162_rn((v1.z - mean) * rstd * w1.z + b1.z,
                                     (v1.w - mean) * rstd * w1.w + b1.w);
    *(uint4*)(out + (size_t)t * DIM + c0) = pk.u;
}

#define LDTW 20   // u32 words per 32-bf16 row (padded)

// ============ 256-thread GEMM, CTA 128x128, 8 warps of 64x32, BK=32 =========
#define A_W2 (128 * LDTW)
#define STG2 (2 * A_W2)

template<int EPI>
__global__ __launch_bounds__(256, 2) void mgemm2_kernel(
    const __nv_bfloat16* __restrict__ A, const __nv_bfloat16* __restrict__ Bw,
    const float* __restrict__ bias, const float* __restrict__ res,
    void* __restrict__ Cv, int Nout, int K)
{
    extern __shared__ uint32_t smw[];
    int tid  = threadIdx.x;
    int wid  = tid >> 5, lane = tid & 31;
    int wm   = wid >> 2, wn = wid & 3;
    int g    = lane >> 2, t4 = lane & 3;
    int m0   = blockIdx.y * 128;
    int n0   = blockIdx.x * 128;
    uint32_t sbase = smem_u32(smw);

    float acc[4][4][4];
    #pragma unroll
    for (int i = 0; i < 4; ++i)
        #pragma unroll
        for (int j = 0; j < 4; ++j)
            #pragma unroll
            for (int k = 0; k < 4; ++k) acc[i][j][k] = 0.0f;

    const int T = K >> 5;

    auto issue = [&](int kt, int s) {
        uint32_t ab = sbase + (uint32_t)(s * STG2) * 4u;
        uint32_t bb = ab + (uint32_t)A_W2 * 4u;
        int k0 = kt << 5;
        #pragma unroll
        for (int i = 0; i < 2; ++i) {
            int c = tid + i * 256;
            int row = c >> 2, cc = c & 3;
            CP_ASYNC16(ab + (uint32_t)(row * LDTW + cc * 4) * 4u,
                       A + (size_t)(m0 + row) * K + k0 + cc * 8);
        }
        #pragma unroll
        for (int i = 0; i < 2; ++i) {
            int c = tid + i * 256;
            int row = c >> 2, cc = c & 3;
            CP_ASYNC16(bb + (uint32_t)(row * LDTW + cc * 4) * 4u,
                       Bw + (size_t)(n0 + row) * K + k0 + cc * 8);
        }
        CP_COMMIT();
    };

    issue(0, 0); issue(1, 1); issue(2, 2);

    int s = 0;
    for (int t = 0; t < T; ++t) {
        CP_WAIT2();
        __syncthreads();
        const uint32_t* As = smw + s * STG2;
        const uint32_t* Bs = As + A_W2;

        #pragma unroll
        for (int ks = 0; ks < 2; ++ks) {
            int kw = ks * 8 + t4;
            uint32_t af[4][4], bf2[4][2];
            #pragma unroll
            for (int mt = 0; mt < 4; ++mt) {
                int r = wm * 64 + mt * 16 + g;
                af[mt][0] = As[r * LDTW + kw];
                af[mt][1] = As[(r + 8) * LDTW + kw];
                af[mt][2] = As[r * LDTW + kw + 4];
                af[mt][3] = As[(r + 8) * LDTW + kw + 4];
            }
            #pragma unroll
            for (int nt = 0; nt < 4; ++nt) {
                int n = wn * 32 + nt * 8 + g;
                bf2[nt][0] = Bs[n * LDTW + kw];
                bf2[nt][1] = Bs[n * LDTW + kw + 4];
            }
            #pragma unroll
            for (int mt = 0; mt < 4; ++mt)
                #pragma unroll
                for (int nt = 0; nt < 4; ++nt)
                    mma_bf16(acc[mt][nt], af[mt], bf2[nt]);
        }
        __syncthreads();
        if (t + 3 < T) issue(t + 3, s); else CP_COMMIT();
        if (++s == 3) s = 0;
    }

    const float kS = 0.70710678118654752440f;
    #pragma unroll
    for (int mt = 0; mt < 4; ++mt) {
        #pragma unroll
        for (int rr = 0; rr < 2; ++rr) {
            int m = m0 + wm * 64 + mt * 16 + rr * 8 + g;
            #pragma unroll
            for (int nt = 0; nt < 4; ++nt) {
                int col = wn * 32 + nt * 8 + t4 * 2;
                float v0 = acc[mt][nt][rr * 2 + 0] + bias[n0 + col];
                float v1 = acc[mt][nt][rr * 2 + 1] + bias[n0 + col + 1];
                if (EPI == 1) {
                    v0 = 0.5f * v0 * (1.0f + erff(v0 * kS));
                    v1 = 0.5f * v1 * (1.0f + erff(v1 * kS));
                }
                if (EPI == 2) {
                    const float* rrow = res + (size_t)m * Nout + n0;
                    float* crow = (float*)Cv + (size_t)m * Nout + n0;
                    *(float2*)(crow + col) = make_float2(v0 + rrow[col], v1 + rrow[col + 1]);
                } else {
                    __nv_bfloat16* crow = (__nv_bfloat16*)Cv + (size_t)m * Nout + n0;
                    *(__nv_bfloat162*)(crow + col) = __floats2bfloat162_rn(v0, v1);
                }
            }
        }
    }
}

// ===== 512-thread proj GEMM, CTA 128x256: +bias+res scatter + fused LN2 =====
#define A_WORDS (128 * LDTW)
#define B_WORDS (256 * LDTW)
#define STAGE_WORDS (A_WORDS + B_WORDS)

__global__ __launch_bounds__(512, 1) void proj_kernel(
    const __nv_bfloat16* __restrict__ A, const __nv_bfloat16* __restrict__ Bw,
    const float* __restrict__ bias, const float* __restrict__ res,
    float* __restrict__ C, __nv_bfloat16* __restrict__ Cln,
    const float* __restrict__ lnw, const float* __restrict__ lnb)
{
    const int Nout = 256, K = 256;
    extern __shared__ uint32_t smw[];
    int tid  = threadIdx.x;
    int wid  = tid >> 5, lane = tid & 31;
    int wm   = wid >> 3, wn = wid & 7;
    int g    = lane >> 2, t4 = lane & 3;
    int m0   = blockIdx.y * 128;
    uint32_t sbase = smem_u32(smw);

    float acc[4][4][4];
    #pragma unroll
    for (int i = 0; i < 4; ++i)
        #pragma unroll
        for (int j = 0; j < 4; ++j)
            #pragma unroll
            for (int k = 0; k < 4; ++k) acc[i][j][k] = 0.0f;

    const int T = K >> 5;

    auto issue = [&](int kt, int s) {
        uint32_t ab = sbase + (uint32_t)(s * STAGE_WORDS) * 4u;
        uint32_t bb = ab + (uint32_t)A_WORDS * 4u;
        int k0 = kt << 5;
        {
            int row = tid >> 2, cc = tid & 3;
            CP_ASYNC16(ab + (uint32_t)(row * LDTW + cc * 4) * 4u,
                       A + (size_t)(m0 + row) * K + k0 + cc * 8);
        }
        #pragma unroll
        for (int i = 0; i < 2; ++i) {
            int c = tid + i * 512;
            int row = c >> 2, cc = c & 3;
            CP_ASYNC16(bb + (uint32_t)(row * LDTW + cc * 4) * 4u,
                       Bw + (size_t)row * K + k0 + cc * 8);
        }
        CP_COMMIT();
    };

    issue(0, 0); issue(1, 1); issue(2, 2);

    int s = 0;
    for (int t = 0; t < T; ++t) {
        CP_WAIT2();
        __syncthreads();
        const uint32_t* As = smw + s * STAGE_WORDS;
        const uint32_t* Bs = As + A_WORDS;

        #pragma unroll
        for (int ks = 0; ks < 2; ++ks) {
            int kw = ks * 8 + t4;
            uint32_t af[4][4], bf2[4][2];
            #pragma unroll
            for (int mt = 0; mt < 4; ++mt) {
                int r = wm * 64 + mt * 16 + g;
                af[mt][0] = As[r * LDTW + kw];
                af[mt][1] = As[(r + 8) * LDTW + kw];
                af[mt][2] = As[r * LDTW + kw + 4];
                af[mt][3] = As[(r + 8) * LDTW + kw + 4];
            }
            #pragma unroll
            for (int nt = 0; nt < 4; ++nt) {
                int n = wn * 32 + nt * 8 + g;
                bf2[nt][0] = Bs[n * LDTW + kw];
                bf2[nt][1] = Bs[n * LDTW + kw + 4];
            }
            #pragma unroll
            for (int mt = 0; mt < 4; ++mt)
                #pragma unroll
                for (int nt = 0; nt < 4; ++nt)
                    mma_bf16(acc[mt][nt], af[mt], bf2[nt]);
        }
        __syncthreads();
        if (t + 3 < T) issue(t + 3, s); else CP_COMMIT();
        if (++s == 3) s = 0;
    }

    __syncthreads();
    float2* p2      = (float2*)smw;
    float2* rowstat = ((float2*)smw) + 4096;

    #pragma unroll
    for (int mt = 0; mt < 4; ++mt) {
        #pragma unroll
        for (int rr = 0; rr < 2; ++rr) {
            int lm = wm * 64 + mt * 16 + rr * 8 + g;
            int dm = win_to_pix(m0 + lm);
            float*       xrow = C   + (size_t)dm * Nout;
            const float* rrow = res + (size_t)dm * Nout;
            float psum = 0.0f, psq = 0.0f;
            #pragma unroll
            for (int nt = 0; nt < 4; ++nt) {
                int col = wn * 32 + nt * 8 + t4 * 2;
                float v0 = acc[mt][nt][rr * 2 + 0] + bias[col]     + rrow[col];
                float v1 = acc[mt][nt][rr * 2 + 1] + bias[col + 1] + rrow[col + 1];
                acc[mt][nt][rr * 2 + 0] = v0;
                acc[mt][nt][rr * 2 + 1] = v1;
                *(float2*)(xrow + col) = make_float2(v0, v1);
                psum += v0 + v1; psq += v0 * v0 + v1 * v1;
            }
            p2[tid * 8 + mt * 2 + rr] = make_float2(psum, psq);
        }
    }
    __syncthreads();
    if (tid < 128) {
        int lm = tid;
        int lwm = lm >> 6, lmt = (lm >> 4) & 3, lrr = (lm >> 3) & 1, lg = lm & 7;
        float s1 = 0.0f, s2 = 0.0f;
        #pragma unroll
        for (int w = 0; w < 8; ++w)
            #pragma unroll
            for (int q = 0; q < 4; ++q) {
                float2 f = p2[(((lwm * 8 + w) << 5) + (lg << 2) + q) * 8 + lmt * 2 + lrr];
                s1 += f.x; s2 += f.y;
            }
        float mean = s1 * (1.0f / 256.0f);
        float var  = s2 * (1.0f / 256.0f) - mean * mean;
        rowstat[lm] = make_float2(mean, rsqrtf(var + 1e-5f));
    }
    __syncthreads();
    #pragma unroll
    for (int mt = 0; mt < 4; ++mt) {
        #pragma unroll
        for (int rr = 0; rr < 2; ++rr) {
            int lm = wm * 64 + mt * 16 + rr * 8 + g;
            float2 st = rowstat[lm];
            int dm = win_to_pix(m0 + lm);
            __nv_bfloat16* lrow = Cln + (size_t)dm * Nout;
            #pragma unroll
            for (int nt = 0; nt < 4; ++nt) {
                int col = wn * 32 + nt * 8 + t4 * 2;
                float v0 = (acc[mt][nt][rr * 2 + 0] - st.x) * st.y * lnw[col]     + lnb[col];
                float v1 = (acc[mt][nt][rr * 2 + 1] - st.x) * st.y * lnw[col + 1] + lnb[col + 1];
                *(__nv_bfloat162*)(lrow + col) = __floats2bfloat162_rn(v0, v1);
            }
        }
    }
}

// ======== MMA attention: CTA per (window,head), 4 warps, reg softmax ========
__global__ __launch_bounds__(128) void attn_kernel(
    const __nv_bfloat16* __restrict__ qkv, const float* __restrict__ comb,
    __nv_bfloat16* __restrict__ out)
{
    __shared__ uint32_t Qs[64 * 20];   // [row][40 bf16], 32 used
    __shared__ uint32_t Ks[64 * 20];
    __shared__ uint32_t Vs[32 * 36];   // transposed V: [d][72 bf16], 64 used

    int blk  = blockIdx.x;
    int h    = blk & (HEADS - 1);
    int wv   = blk >> 3;
    int wi   = wv & (NWIN - 1);
    int tid  = threadIdx.x;
    int warp = tid >> 5, lane = tid & 31;
    int g    = lane >> 2, t4 = lane & 3;
    const float scale = 0.17677669529663688f;

    // zero-fill (padding rows must be 0)
    for (int i = tid; i < 64 * 20; i += 128) { Qs[i] = 0u; Ks[i] = 0u; }
    for (int i = tid; i < 32 * 36; i += 128) Vs[i] = 0u;
    __syncthreads();

    // load q/k (row-major) and v (transposed)
    const __nv_bfloat16* base = qkv + (size_t)wv * NTOK * 768 + h * HD;
    __nv_bfloat16* Vh = (__nv_bfloat16*)Vs;
    for (int idx = tid; idx < NTOK * 16; idx += 128) {
        int n = idx >> 4, dp = idx & 15;          // dp = d/2
        const __nv_bfloat16* p = base + (size_t)n * 768 + dp * 2;
        Qs[n * 20 + dp] = *(const uint32_t*)(p);
        Ks[n * 20 + dp] = *(const uint32_t*)(p + 256);
        __nv_bfloat162 v2 = *(const __nv_bfloat162*)(p + 512);
        Vh[(dp * 2 + 0) * 72 + n] = v2.x;
        Vh[(dp * 2 + 1) * 72 + n] = v2.y;
    }
    __syncthreads();

    // ---- S = Q K^T : rows 16*warp..+15, 7 col-tiles ----
    float p[7][4];
    #pragma unroll
    for (int j = 0; j < 7; ++j)
        #pragma unroll
        for (int e = 0; e < 4; ++e) p[j][e] = 0.0f;

    int r0 = 16 * warp + g, r1 = r0 + 8;
    #pragma unroll
    for (int ks = 0; ks < 2; ++ks) {
        int kw = ks * 8 + t4;
        uint32_t a[4];
        a[0] = Qs[r0 * 20 + kw];
        a[1] = Qs[r1 * 20 + kw];
        a[2] = Qs[r0 * 20 + kw + 4];
        a[3] = Qs[r1 * 20 + kw + 4];
        #pragma unroll
        for (int j = 0; j < 7; ++j) {
            uint32_t b[2];
            b[0] = Ks[(8 * j + g) * 20 + kw];
            b[1] = Ks[(8 * j + g) * 20 + kw + 4];
            mma_bf16(p[j], a, b);
        }
    }

    // ---- bias+mask+scale, register softmax (quad reductions) ----
    const float* cb = comb + (size_t)(wi * 8 + h) * (NTOK * NTOK);
    float mx0 = -1e30f, mx1 = -1e30f;
    #pragma unroll
    for (int j = 0; j < 7; ++j) {
        int c0 = 8 * j + 2 * t4, c1 = c0 + 1;
        p[j][0] = (r0 < NTOK && c0 < NTOK) ? p[j][0] * scale + cb[r0 * NTOK + c0] : -1e30f;
        p[j][1] = (r0 < NTOK && c1 < NTOK) ? p[j][1] * scale + cb[r0 * NTOK + c1] : -1e30f;
        p[j][2] = (r1 < NTOK && c0 < NTOK) ? p[j][2] * scale + cb[r1 * NTOK + c0] : -1e30f;
        p[j][3] = (r1 < NTOK && c1 < NTOK) ? p[j][3] * scale + cb[r1 * NTOK + c1] : -1e30f;
        mx0 = fmaxf(mx0, fmaxf(p[j][0], p[j][1]));
        mx1 = fmaxf(mx1, fmaxf(p[j][2], p[j][3]));
    }
    mx0 = fmaxf(mx0, __shfl_xor_sync(0xffffffffu, mx0, 1));
    mx0 = fmaxf(mx0, __shfl_xor_sync(0xffffffffu, mx0, 2));
    mx1 = fmaxf(mx1, __shfl_xor_sync(0xffffffffu, mx1, 1));
    mx1 = fmaxf(mx1, __shfl_xor_sync(0xffffffffu, mx1, 2));

    float s0 = 0.0f, s1 = 0.0f;
    #pragma unroll
    for (int j = 0; j < 7; ++j) {
        p[j][0] = __expf(p[j][0] - mx0); s0 += p[j][0];
        p[j][1] = __expf(p[j][1] - mx0); s0 += p[j][1];
        p[j][2] = __expf(p[j][2] - mx1); s1 += p[j][2];
        p[j][3] = __expf(p[j][3] - mx1); s1 += p[j][3];
    }
    s0 += __shfl_xor_sync(0xffffffffu, s0, 1);
    s0 += __shfl_xor_sync(0xffffffffu, s0, 2);
    s1 += __shfl_xor_sync(0xffffffffu, s1, 1);
    s1 += __shfl_xor_sync(0xffffffffu, s1, 2);
    float i0 = 1.0f / s0, i1 = 1.0f / s1;

    uint32_t ab0[7], ab1[7];
    #pragma unroll
    for (int j = 0; j < 7; ++j) {
        ab0[j] = packbf(p[j][0] * i0, p[j][1] * i0);
        ab1[j] = packbf(p[j][2] * i1, p[j][3] * i1);
    }

    // ---- O = A V : A-fragments direct from softmax regs, V transposed ----
    float o[4][4];
    #pragma unroll
    for (int nt = 0; nt < 4; ++nt)
        #pragma unroll
        for (int e = 0; e < 4; ++e) o[nt][e] = 0.0f;

    #pragma unroll
    for (int kt = 0; kt < 4; ++kt) {
        uint32_t a[4];
        a[0] = ab0[2 * kt];
        a[1] = ab1[2 * kt];
        a[2] = (kt < 3) ? ab0[2 * kt + 1] : 0u;
        a[3] = (kt < 3) ? ab1[2 * kt + 1] : 0u;
        int kwv = t4 + 8 * kt;
        #pragma unroll
        for (int nt = 0; nt < 4; ++nt) {
            uint32_t b[2];
            b[0] = Vs[(8 * nt + g) * 36 + kwv];
            b[1] = Vs[(8 * nt + g) * 36 + kwv + 4];
            mma_bf16(o[nt], a, b);
        }
    }

    // ---- store ----
    if (r0 < NTOK) {
        __nv_bfloat16* orow = out + (size_t)(wv * NTOK + r0) * DIM + h * HD + 2 * t4;
        #pragma unroll
        for (int nt = 0; nt < 4; ++nt)
            *(__nv_bfloat162*)(orow + 8 * nt) = __floats2bfloat162_rn(o[nt][0], o[nt][1]);
    }
    if (r1 < NTOK) {
        __nv_bfloat16* orow = out + (size_t)(wv * NTOK + r1) * DIM + h * HD + 2 * t4;
        #pragma unroll
        for (int nt = 0; nt < 4; ++nt)
            *(__nv_bfloat162*)(orow + 8 * nt) = __floats2bfloat162_rn(o[nt][2], o[nt][3]);
    }
}

// ---------------- launch --------------------------------------------------
extern "C" void kernel_launch(void* const* d_in, const int* in_sizes, int n_in,
                              void* d_out, int out_size) {
    const float* x     = (const float*)d_in[0];
    const float* n1w   = (const float*)d_in[1];
    const float* n1b   = (const float*)d_in[2];
    const float* qkvw  = (const float*)d_in[3];
    const float* qkvb  = (const float*)d_in[4];
    const float* rpb   = (const float*)d_in[5];
    const float* projw = (const float*)d_in[6];
    const float* projb = (const float*)d_in[7];
    const float* n2w   = (const float*)d_in[8];
    const float* n2b   = (const float*)d_in[9];
    const float* fc1w  = (const float*)d_in[10];
    const float* fc1b  = (const float*)d_in[11];
    const float* fc2w  = (const float*)d_in[12];
    const float* fc2b  = (const float*)d_in[13];
    const int*   relix = (const int*)d_in[14];
    const float* mask  = (const float*)d_in[15];
    float* out = (float*)d_out;

    __nv_bfloat16 *bufA, *bufB, *bufC, *bufW;
    float *bufX, *combp;
    cudaGetSymbolAddress((void**)&bufA, g_bufA);
    cudaGetSymbolAddress((void**)&bufB, g_bufB);
    cudaGetSymbolAddress((void**)&bufC, g_bufC);
    cudaGetSymbolAddress((void**)&bufX, g_bufX);
    cudaGetSymbolAddress((void**)&bufW, g_bufW);
    cudaGetSymbolAddress((void**)&combp, g_comb);

    __nv_bfloat16* wqkv = bufW;
    __nv_bfloat16* wprj = wqkv + 196608;
    __nv_bfloat16* wfc1 = wprj + 65536;
    __nv_bfloat16* wfc2 = wfc1 + 262144;

    const int LN_BLOCKS = T_TOK / 8;
    const int MT = T_TOK / 128;             // 784
    const int SH2  = 3 * STG2 * 4;          // 61440
    const int SHP  = 3 * STAGE_WORDS * 4;   // 92160

    cudaFuncSetAttribute(mgemm2_kernel<0>, cudaFuncAttributeMaxDynamicSharedMemorySize, SH2);
    cudaFuncSetAttribute(mgemm2_kernel<1>, cudaFuncAttributeMaxDynamicSharedMemorySize, SH2);
    cudaFuncSetAttribute(mgemm2_kernel<2>, cudaFuncAttributeMaxDynamicSharedMemorySize, SH2);
    cudaFuncSetAttribute(proj_kernel, cudaFuncAttributeMaxDynamicSharedMemorySize, SHP);

    // 0) weight conversion + combined bias table
    convw_kernel<<<(786432 + 255) / 256, 256>>>(qkvw, projw, fc1w, fc2w, bufW);
    comb_kernel<<<NWIN * HEADS, 256>>>(rpb, relix, mask, combp);

    // 1) LN1 + shift + window partition -> bufB (bf16)
    ln_kernel<<<LN_BLOCKS, 256>>>(x, n1w, n1b, bufB);

    // 2) qkv GEMM -> bufA [T,768] (bf16)
    mgemm2_kernel<0><<<dim3(768 / 128, MT), 256, SH2>>>(
        bufB, wqkv, qkvb, nullptr, bufA, 768, DIM);

    // 3) MMA attention -> bufB (bf16, window order)
    attn_kernel<<<(T_TOK / NTOK) * HEADS, 128>>>(bufA, combp, bufB);

    // 4) proj + scatter + residual + fused LN2 -> bufX (fp32), bufC (bf16)
    proj_kernel<<<dim3(1, MT), 512, SHP>>>(
        bufB, wprj, projb, x, bufX, bufC, n2w, n2b);

    // 5) fc1 + GELU -> bufA [T,1024] (bf16)
    mgemm2_kernel<1><<<dim3(HIDDEN / 128, MT), 256, SH2>>>(
        bufC, wfc1, fc1b, nullptr, bufA, HIDDEN, DIM);

    // 6) fc2 + residual -> d_out (fp32)
    mgemm2_kernel<2><<<dim3(DIM / 128, MT), 256, SH2>>>(
        bufA, wfc2, fc2b, bufX, out, DIM, HIDDEN);
}

// round 11
// speedup vs baseline: 6.2655x; 1.0317x over previous
#include <cuda_runtime.h>
#include <cuda_bf16.h>
#include <cstdint>
#include <math.h>

// ---------------- problem constants ----------------
#define BATCH   32
#define HH      56
#define WIMG    56
#define DIM     256
#define HEADS   8
#define HD      32
#define WS      7
#define SHIFT   3
#define NTOK    49
#define NWIN    64
#define HIDDEN  1024
#define T_TOK   100352

// ---------------- scratch ----------------
__device__ __nv_bfloat16 g_bufA[(size_t)T_TOK * 1024]; // qkv [T,768] / fc1-out [T,1024]
__device__ __nv_bfloat16 g_bufB[(size_t)T_TOK * 256];  // LN1-out / attn-out
__device__ __nv_bfloat16 g_bufC[(size_t)T_TOK * 256];  // LN2-out
__device__ float         g_bufX[(size_t)T_TOK * 256];  // x after first residual (fp32)
__device__ __nv_bfloat16 g_bufW[786432];               // bf16 weights: qkv|proj|fc1|fc2
__device__ float         g_comb[NWIN * HEADS * NTOK * NTOK]; // rpb-gather + mask

// ---------------- helpers ----------------
__device__ __forceinline__ uint32_t smem_u32(const void* p) {
    uint32_t a;
    asm("{ .reg .u64 t; cvta.to.shared.u64 t, %1; cvt.u32.u64 %0, t; }" : "=r"(a) : "l"(p));
    return a;
}
#define CP_ASYNC16(dst, src) \
    asm volatile("cp.async.cg.shared.global [%0], [%1], 16;\n" :: "r"(dst), "l"(src))
#define CP_COMMIT() asm volatile("cp.async.commit_group;\n" ::: "memory")
#define CP_WAIT1()  asm volatile("cp.async.wait_group 1;\n" ::: "memory")
#define CP_WAIT2()  asm volatile("cp.async.wait_group 2;\n" ::: "memory")

#define LDSM_X4(r0, r1, r2, r3, addr) \
    asm volatile("ldmatrix.sync.aligned.m8n8.x4.shared.b16 {%0,%1,%2,%3}, [%4];" \
        : "=r"(r0), "=r"(r1), "=r"(r2), "=r"(r3) : "r"(addr))

__device__ __forceinline__ void mma_bf16(float* d, const uint32_t* a, const uint32_t* b) {
    asm volatile(
        "mma.sync.aligned.m16n8k16.row.col.f32.bf16.bf16.f32 "
        "{%0,%1,%2,%3}, {%4,%5,%6,%7}, {%8,%9}, {%0,%1,%2,%3};"
        : "+f"(d[0]), "+f"(d[1]), "+f"(d[2]), "+f"(d[3])
        : "r"(a[0]), "r"(a[1]), "r"(a[2]), "r"(a[3]), "r"(b[0]), "r"(b[1]));
}

__device__ __forceinline__ uint32_t packbf(float x, float y) {
    __nv_bfloat162 h = __floats2bfloat162_rn(x, y);
    return *(uint32_t*)&h;
}

__device__ __forceinline__ int win_to_pix(int m) {
    int n_in = m % NTOK;
    int wv   = m / NTOK;
    int bimg = wv >> 6;
    int wi   = wv & 63;
    int wh   = wi >> 3;
    int wc   = wi & 7;
    int i    = n_in / WS;
    int j    = n_in - i * WS;
    int pr   = wh * WS + i + SHIFT; if (pr >= HH)   pr -= HH;
    int pc   = wc * WS + j + SHIFT; if (pc >= WIMG) pc -= WIMG;
    return bimg * (HH * WIMG) + pr * WIMG + pc;
}

// ---------------- all weights -> bf16, one kernel ----------------
__global__ void convw_kernel(const float* __restrict__ s0, const float* __restrict__ s1,
                             const float* __restrict__ s2, const float* __restrict__ s3,
                             __nv_bfloat16* __restrict__ d) {
    int i = blockIdx.x * 256 + threadIdx.x;
    if (i >= 786432) return;
    float v;
    if (i < 196608)      v = s0[i];
    else if (i < 262144) v = s1[i - 196608];
    else if (i < 524288) v = s2[i - 262144];
    else                 v = s3[i - 524288];
    d[i] = __float2bfloat16_rn(v);
}

// ---------------- combined bias table ----------------
__global__ void comb_kernel(const float* __restrict__ rpb, const int* __restrict__ relix,
                            const float* __restrict__ mask, float* __restrict__ comb) {
    int wh = blockIdx.x;
    int wi = wh >> 3, h = wh & 7;
    for (int e = threadIdx.x; e < NTOK * NTOK; e += 256)
        comb[(size_t)wh * (NTOK * NTOK) + e] =
            rpb[relix[e] * HEADS + h] + mask[(size_t)wi * (NTOK * NTOK) + e];
}

// ---------------- LayerNorm + shift + window gather, bf16 output ------------
__global__ __launch_bounds__(256) void ln_kernel(
    const float* __restrict__ x, const float* __restrict__ w,
    const float* __restrict__ b, __nv_bfloat16* __restrict__ out)
{
    int t    = blockIdx.x * 8 + (threadIdx.x >> 5);
    int lane = threadIdx.x & 31;
    int src  = win_to_pix(t);

    const float4* px = (const float4*)(x + (size_t)src * DIM) + lane * 2;
    float4 v0 = px[0], v1 = px[1];

    float s  = v0.x + v0.y + v0.z + v0.w + v1.x + v1.y + v1.z + v1.w;
    float ss = v0.x*v0.x + v0.y*v0.y + v0.z*v0.z + v0.w*v0.w
             + v1.x*v1.x + v1.y*v1.y + v1.z*v1.z + v1.w*v1.w;
    #pragma unroll
    for (int o = 16; o; o >>= 1) {
        s  += __shfl_xor_sync(0xffffffffu, s,  o);
        ss += __shfl_xor_sync(0xffffffffu, ss, o);
    }
    float mean = s * (1.0f / DIM);
    float var  = ss * (1.0f / DIM) - mean * mean;
    float rstd = rsqrtf(var + 1e-5f);

    int c0 = lane * 8;
    const float4* pw = (const float4*)(w + c0);
    const float4* pb = (const float4*)(b + c0);
    float4 w0 = pw[0], w1 = pw[1], b0 = pb[0], b1 = pb[1];

    union { __nv_bfloat162 h2[4]; uint4 u; } pk;
    pk.h2[0] = __floats2bfloat162_rn((v0.x - mean) * rstd * w0.x + b0.x,
                                     (v0.y - mean) * rstd * w0.y + b0.y);
    pk.h2[1] = __floats2bfloat162_rn((v0.z - mean) * rstd * w0.z + b0.z,
                                     (v0.w - mean) * rstd * w0.w + b0.w);
    pk.h2[2] = __floats2bfloat162_rn((v1.x - mean) * rstd * w1.x + b1.x,
                                     (v1.y - mean) * rstd * w1.y + b1.y);
    pk.h2[3] = __floats2bfloat162_rn((v1.z - mean) * rstd * w1.z + b1.z,
                                     (v1.w - mean) * rstd * w1.w + b1.w);
    *(uint4*)(out + (size_t)t * DIM + c0) = pk.u;
}

// ======= 256-thread GEMM, CTA 128x128, 8 warps of 64x32, BK=64, ldmatrix ====
#define LDW 36                    // u32 words per 64-bf16 row (padded; 144B)
#define A_W3 (128 * LDW)          // 4608 words
#define STG3 (2 * A_W3)           // 9216 words / stage, 2 stages

template<int EPI>
__global__ __launch_bounds__(256, 2) void mgemm3_kernel(
    const __nv_bfloat16* __restrict__ A, const __nv_bfloat16* __restrict__ Bw,
    const float* __restrict__ bias, const float* __restrict__ res,
    void* __restrict__ Cv, int Nout, int K)
{
    extern __shared__ uint32_t smw[];
    int tid  = threadIdx.x;
    int wid  = tid >> 5, lane = tid & 31;
    int wm   = wid >> 2, wn = wid & 3;
    int g    = lane >> 2, t4 = lane & 3;
    int lr   = lane & 15, lc = lane >> 4;     // ldmatrix addressing
    int m0   = blockIdx.y * 128;
    int n0   = blockIdx.x * 128;
    uint32_t sbase = smem_u32(smw);

    float acc[4][4][4];
    #pragma unroll
    for (int i = 0; i < 4; ++i)
        #pragma unroll
        for (int j = 0; j < 4; ++j)
            #pragma unroll
            for (int k = 0; k < 4; ++k) acc[i][j][k] = 0.0f;

    const int T = K >> 6;   // K/64 tiles

    auto issue = [&](int kt, int s) {
        uint32_t ab = sbase + (uint32_t)(s * STG3) * 4u;
        uint32_t bb = ab + (uint32_t)A_W3 * 4u;
        int k0 = kt << 6;
        #pragma unroll
        for (int i = 0; i < 4; ++i) {
            int c = tid + i * 256;
            int row = c >> 3, cc = c & 7;
            CP_ASYNC16(ab + (uint32_t)(row * LDW + cc * 4) * 4u,
                       A + (size_t)(m0 + row) * K + k0 + cc * 8);
        }
        #pragma unroll
        for (int i = 0; i < 4; ++i) {
            int c = tid + i * 256;
            int row = c >> 3, cc = c & 7;
            CP_ASYNC16(bb + (uint32_t)(row * LDW + cc * 4) * 4u,
                       Bw + (size_t)(n0 + row) * K + k0 + cc * 8);
        }
        CP_COMMIT();
    };

    issue(0, 0); issue(1, 1);

    for (int t = 0; t < T; ++t) {
        int s = t & 1;
        CP_WAIT1();
        __syncthreads();
        uint32_t As = sbase + (uint32_t)(s * STG3) * 4u;
        uint32_t Bs = As + (uint32_t)A_W3 * 4u;

        #pragma unroll
        for (int ks = 0; ks < 4; ++ks) {
            int kw = ks * 8 + lc * 4;
            uint32_t af[4][4], bf2[4][2];
            #pragma unroll
            for (int mt = 0; mt < 4; ++mt) {
                uint32_t ad = As + (uint32_t)((wm * 64 + mt * 16 + lr) * LDW + kw) * 4u;
                LDSM_X4(af[mt][0], af[mt][1], af[mt][2], af[mt][3], ad);
            }
            #pragma unroll
            for (int np = 0; np < 2; ++np) {
                uint32_t bd = Bs + (uint32_t)((wn * 32 + np * 16 + lr) * LDW + kw) * 4u;
                LDSM_X4(bf2[2 * np][0], bf2[2 * np + 1][0],
                        bf2[2 * np][1], bf2[2 * np + 1][1], bd);
            }
            #pragma unroll
            for (int mt = 0; mt < 4; ++mt)
                #pragma unroll
                for (int nt = 0; nt < 4; ++nt)
                    mma_bf16(acc[mt][nt], af[mt], bf2[nt]);
        }
        __syncthreads();
        if (t + 2 < T) issue(t + 2, s); else CP_COMMIT();
    }

    const float kS = 0.70710678118654752440f;
    #pragma unroll
    for (int mt = 0; mt < 4; ++mt) {
        #pragma unroll
        for (int rr = 0; rr < 2; ++rr) {
            int m = m0 + wm * 64 + mt * 16 + rr * 8 + g;
            #pragma unroll
            for (int nt = 0; nt < 4; ++nt) {
                int col = wn * 32 + nt * 8 + t4 * 2;
                float v0 = acc[mt][nt][rr * 2 + 0] + bias[n0 + col];
                float v1 = acc[mt][nt][rr * 2 + 1] + bias[n0 + col + 1];
                if (EPI == 1) {
                    v0 = 0.5f * v0 * (1.0f + erff(v0 * kS));
                    v1 = 0.5f * v1 * (1.0f + erff(v1 * kS));
                }
                if (EPI == 2) {
                    const float* rrow = res + (size_t)m * Nout + n0;
                    float* crow = (float*)Cv + (size_t)m * Nout + n0;
                    *(float2*)(crow + col) = make_float2(v0 + rrow[col], v1 + rrow[col + 1]);
                } else {
                    __nv_bfloat16* crow = (__nv_bfloat16*)Cv + (size_t)m * Nout + n0;
                    *(__nv_bfloat162*)(crow + col) = __floats2bfloat162_rn(v0, v1);
                }
            }
        }
    }
}

// ===== 512-thread proj GEMM, CTA 128x256: +bias+res scatter + fused LN2 =====
#define LDTW 20
#define A_WORDS (128 * LDTW)
#define B_WORDS (256 * LDTW)
#define STAGE_WORDS (A_WORDS + B_WORDS)

__global__ __launch_bounds__(512, 1) void proj_kernel(
    const __nv_bfloat16* __restrict__ A, const __nv_bfloat16* __restrict__ Bw,
    const float* __restrict__ bias, const float* __restrict__ res,
    float* __restrict__ C, __nv_bfloat16* __restrict__ Cln,
    const float* __restrict__ lnw, const float* __restrict__ lnb)
{
    const int Nout = 256, K = 256;
    extern __shared__ uint32_t smw[];
    int tid  = threadIdx.x;
    int wid  = tid >> 5, lane = tid & 31;
    int wm   = wid >> 3, wn = wid & 7;
    int g    = lane >> 2, t4 = lane & 3;
    int m0   = blockIdx.y * 128;
    uint32_t sbase = smem_u32(smw);

    float acc[4][4][4];
    #pragma unroll
    for (int i = 0; i < 4; ++i)
        #pragma unroll
        for (int j = 0; j < 4; ++j)
            #pragma unroll
            for (int k = 0; k < 4; ++k) acc[i][j][k] = 0.0f;

    const int T = K >> 5;

    auto issue = [&](int kt, int s) {
        uint32_t ab = sbase + (uint32_t)(s * STAGE_WORDS) * 4u;
        uint32_t bb = ab + (uint32_t)A_WORDS * 4u;
        int k0 = kt << 5;
        {
            int row = tid >> 2, cc = tid & 3;
            CP_ASYNC16(ab + (uint32_t)(row * LDTW + cc * 4) * 4u,
                       A + (size_t)(m0 + row) * K + k0 + cc * 8);
        }
        #pragma unroll
        for (int i = 0; i < 2; ++i) {
            int c = tid + i * 512;
            int row = c >> 2, cc = c & 3;
            CP_ASYNC16(bb + (uint32_t)(row * LDTW + cc * 4) * 4u,
                       Bw + (size_t)row * K + k0 + cc * 8);
        }
        CP_COMMIT();
    };

    issue(0, 0); issue(1, 1); issue(2, 2);

    int s = 0;
    for (int t = 0; t < T; ++t) {
        CP_WAIT2();
        __syncthreads();
        const uint32_t* As = smw + s * STAGE_WORDS;
        const uint32_t* Bs = As + A_WORDS;

        #pragma unroll
        for (int ks = 0; ks < 2; ++ks) {
            int kw = ks * 8 + t4;
            uint32_t af[4][4], bf2[4][2];
            #pragma unroll
            for (int mt = 0; mt < 4; ++mt) {
                int r = wm * 64 + mt * 16 + g;
                af[mt][0] = As[r * LDTW + kw];
                af[mt][1] = As[(r + 8) * LDTW + kw];
                af[mt][2] = As[r * LDTW + kw + 4];
                af[mt][3] = As[(r + 8) * LDTW + kw + 4];
            }
            #pragma unroll
            for (int nt = 0; nt < 4; ++nt) {
                int n = wn * 32 + nt * 8 + g;
                bf2[nt][0] = Bs[n * LDTW + kw];
                bf2[nt][1] = Bs[n * LDTW + kw + 4];
            }
            #pragma unroll
            for (int mt = 0; mt < 4; ++mt)
                #pragma unroll
                for (int nt = 0; nt < 4; ++nt)
                    mma_bf16(acc[mt][nt], af[mt], bf2[nt]);
        }
        __syncthreads();
        if (t + 3 < T) issue(t + 3, s); else CP_COMMIT();
        if (++s == 3) s = 0;
    }

    __syncthreads();
    float2* p2      = (float2*)smw;
    float2* rowstat = ((float2*)smw) + 4096;

    #pragma unroll
    for (int mt = 0; mt < 4; ++mt) {
        #pragma unroll
        for (int rr = 0; rr < 2; ++rr) {
            int lm = wm * 64 + mt * 16 + rr * 8 + g;
            int dm = win_to_pix(m0 + lm);
            float*       xrow = C   + (size_t)dm * Nout;
            const float* rrow = res + (size_t)dm * Nout;
            float psum = 0.0f, psq = 0.0f;
            #pragma unroll
            for (int nt = 0; nt < 4; ++nt) {
                int col = wn * 32 + nt * 8 + t4 * 2;
                float v0 = acc[mt][nt][rr * 2 + 0] + bias[col]     + rrow[col];
                float v1 = acc[mt][nt][rr * 2 + 1] + bias[col + 1] + rrow[col + 1];
                acc[mt][nt][rr * 2 + 0] = v0;
                acc[mt][nt][rr * 2 + 1] = v1;
                *(float2*)(xrow + col) = make_float2(v0, v1);
                psum += v0 + v1; psq += v0 * v0 + v1 * v1;
            }
            p2[tid * 8 + mt * 2 + rr] = make_float2(psum, psq);
        }
    }
    __syncthreads();
    if (tid < 128) {
        int lm = tid;
        int lwm = lm >> 6, lmt = (lm >> 4) & 3, lrr = (lm >> 3) & 1, lg = lm & 7;
        float s1 = 0.0f, s2 = 0.0f;
        #pragma unroll
        for (int w = 0; w < 8; ++w)
            #pragma unroll
            for (int q = 0; q < 4; ++q) {
                float2 f = p2[(((lwm * 8 + w) << 5) + (lg << 2) + q) * 8 + lmt * 2 + lrr];
                s1 += f.x; s2 += f.y;
            }
        float mean = s1 * (1.0f / 256.0f);
        float var  = s2 * (1.0f / 256.0f) - mean * mean;
        rowstat[lm] = make_float2(mean, rsqrtf(var + 1e-5f));
    }
    __syncthreads();
    #pragma unroll
    for (int mt = 0; mt < 4; ++mt) {
        #pragma unroll
        for (int rr = 0; rr < 2; ++rr) {
            int lm = wm * 64 + mt * 16 + rr * 8 + g;
            float2 st = rowstat[lm];
            int dm = win_to_pix(m0 + lm);
            __nv_bfloat16* lrow = Cln + (size_t)dm * Nout;
            #pragma unroll
            for (int nt = 0; nt < 4; ++nt) {
                int col = wn * 32 + nt * 8 + t4 * 2;
                float v0 = (acc[mt][nt][rr * 2 + 0] - st.x) * st.y * lnw[col]     + lnb[col];
                float v1 = (acc[mt][nt][rr * 2 + 1] - st.x) * st.y * lnw[col + 1] + lnb[col + 1];
                *(__nv_bfloat162*)(lrow + col) = __floats2bfloat162_rn(v0, v1);
            }
        }
    }
}

// ======== MMA attention: CTA per (window,head), 4 warps, reg softmax ========
__global__ __launch_bounds__(128) void attn_kernel(
    const __nv_bfloat16* __restrict__ qkv, const float* __restrict__ comb,
    __nv_bfloat16* __restrict__ out)
{
    __shared__ uint32_t Qs[64 * 20];
    __shared__ uint32_t Ks[64 * 20];
    __shared__ uint32_t Vs[32 * 36];

    int blk  = blockIdx.x;
    int h    = blk & (HEADS - 1);
    int wv   = blk >> 3;
    int wi   = wv & (NWIN - 1);
    int tid  = threadIdx.x;
    int warp = tid >> 5, lane = tid & 31;
    int g    = lane >> 2, t4 = lane & 3;
    const float scale = 0.17677669529663688f;

    for (int i = tid; i < 64 * 20; i += 128) { Qs[i] = 0u; Ks[i] = 0u; }
    for (int i = tid; i < 32 * 36; i += 128) Vs[i] = 0u;
    __syncthreads();

    const __nv_bfloat16* base = qkv + (size_t)wv * NTOK * 768 + h * HD;
    __nv_bfloat16* Vh = (__nv_bfloat16*)Vs;
    for (int idx = tid; idx < NTOK * 16; idx += 128) {
        int n = idx >> 4, dp = idx & 15;
        const __nv_bfloat16* p = base + (size_t)n * 768 + dp * 2;
        Qs[n * 20 + dp] = *(const uint32_t*)(p);
        Ks[n * 20 + dp] = *(const uint32_t*)(p + 256);
        __nv_bfloat162 v2 = *(const __nv_bfloat162*)(p + 512);
        Vh[(dp * 2 + 0) * 72 + n] = v2.x;
        Vh[(dp * 2 + 1) * 72 + n] = v2.y;
    }
    __syncthreads();

    float p[7][4];
    #pragma unroll
    for (int j = 0; j < 7; ++j)
        #pragma unroll
        for (int e = 0; e < 4; ++e) p[j][e] = 0.0f;

    int r0 = 16 * warp + g, r1 = r0 + 8;
    #pragma unroll
    for (int ks = 0; ks < 2; ++ks) {
        int kw = ks * 8 + t4;
        uint32_t a[4];
        a[0] = Qs[r0 * 20 + kw];
        a[1] = Qs[r1 * 20 + kw];
        a[2] = Qs[r0 * 20 + kw + 4];
        a[3] = Qs[r1 * 20 + kw + 4];
        #pragma unroll
        for (int j = 0; j < 7; ++j) {
            uint32_t b[2];
            b[0] = Ks[(8 * j + g) * 20 + kw];
            b[1] = Ks[(8 * j + g) * 20 + kw + 4];
            mma_bf16(p[j], a, b);
        }
    }

    const float* cb = comb + (size_t)(wi * 8 + h) * (NTOK * NTOK);
    float mx0 = -1e30f, mx1 = -1e30f;
    #pragma unroll
    for (int j = 0; j < 7; ++j) {
        int c0 = 8 * j + 2 * t4, c1 = c0 + 1;
        p[j][0] = (r0 < NTOK && c0 < NTOK) ? p[j][0] * scale + cb[r0 * NTOK + c0] : -1e30f;
        p[j][1] = (r0 < NTOK && c1 < NTOK) ? p[j][1] * scale + cb[r0 * NTOK + c1] : -1e30f;
        p[j][2] = (r1 < NTOK && c0 < NTOK) ? p[j][2] * scale + cb[r1 * NTOK + c0] : -1e30f;
        p[j][3] = (r1 < NTOK && c1 < NTOK) ? p[j][3] * scale + cb[r1 * NTOK + c1] : -1e30f;
        mx0 = fmaxf(mx0, fmaxf(p[j][0], p[j][1]));
        mx1 = fmaxf(mx1, fmaxf(p[j][2], p[j][3]));
    }
    mx0 = fmaxf(mx0, __shfl_xor_sync(0xffffffffu, mx0, 1));
    mx0 = fmaxf(mx0, __shfl_xor_sync(0xffffffffu, mx0, 2));
    mx1 = fmaxf(mx1, __shfl_xor_sync(0xffffffffu, mx1, 1));
    mx1 = fmaxf(mx1, __shfl_xor_sync(0xffffffffu, mx1, 2));

    float s0 = 0.0f, s1 = 0.0f;
    #pragma unroll
    for (int j = 0; j < 7; ++j) {
        p[j][0] = __expf(p[j][0] - mx0); s0 += p[j][0];
        p[j][1] = __expf(p[j][1] - mx0); s0 += p[j][1];
        p[j][2] = __expf(p[j][2] - mx1); s1 += p[j][2];
        p[j][3] = __expf(p[j][3] - mx1); s1 += p[j][3];
    }
    s0 += __shfl_xor_sync(0xffffffffu, s0, 1);
    s0 += __shfl_xor_sync(0xffffffffu, s0, 2);
    s1 += __shfl_xor_sync(0xffffffffu, s1, 1);
    s1 += __shfl_xor_sync(0xffffffffu, s1, 2);
    float i0 = 1.0f / s0, i1 = 1.0f / s1;

    uint32_t ab0[7], ab1[7];
    #pragma unroll
    for (int j = 0; j < 7; ++j) {
        ab0[j] = packbf(p[j][0] * i0, p[j][1] * i0);
        ab1[j] = packbf(p[j][2] * i1, p[j][3] * i1);
    }

    float o[4][4];
    #pragma unroll
    for (int nt = 0; nt < 4; ++nt)
        #pragma unroll
        for (int e = 0; e < 4; ++e) o[nt][e] = 0.0f;

    #pragma unroll
    for (int kt = 0; kt < 4; ++kt) {
        uint32_t a[4];
        a[0] = ab0[2 * kt];
        a[1] = ab1[2 * kt];
        a[2] = (kt < 3) ? ab0[2 * kt + 1] : 0u;
        a[3] = (kt < 3) ? ab1[2 * kt + 1] : 0u;
        int kwv = t4 + 8 * kt;
        #pragma unroll
        for (int nt = 0; nt < 4; ++nt) {
            uint32_t b[2];
            b[0] = Vs[(8 * nt + g) * 36 + kwv];
            b[1] = Vs[(8 * nt + g) * 36 + kwv + 4];
            mma_bf16(o[nt], a, b);
        }
    }

    if (r0 < NTOK) {
        __nv_bfloat16* orow = out + (size_t)(wv * NTOK + r0) * DIM + h * HD + 2 * t4;
        #pragma unroll
        for (int nt = 0; nt < 4; ++nt)
            *(__nv_bfloat162*)(orow + 8 * nt) = __floats2bfloat162_rn(o[nt][0], o[nt][1]);
    }
    if (r1 < NTOK) {
        __nv_bfloat16* orow = out + (size_t)(wv * NTOK + r1) * DIM + h * HD + 2 * t4;
        #pragma unroll
        for (int nt = 0; nt < 4; ++nt)
            *(__nv_bfloat162*)(orow + 8 * nt) = __floats2bfloat162_rn(o[nt][2], o[nt][3]);
    }
}

// ---------------- launch --------------------------------------------------
extern "C" void kernel_launch(void* const* d_in, const int* in_sizes, int n_in,
                              void* d_out, int out_size) {
    const float* x     = (const float*)d_in[0];
    const float* n1w   = (const float*)d_in[1];
    const float* n1b   = (const float*)d_in[2];
    const float* qkvw  = (const float*)d_in[3];
    const float* qkvb  = (const float*)d_in[4];
    const float* rpb   = (const float*)d_in[5];
    const float* projw = (const float*)d_in[6];
    const float* projb = (const float*)d_in[7];
    const float* n2w   = (const float*)d_in[8];
    const float* n2b   = (const float*)d_in[9];
    const float* fc1w  = (const float*)d_in[10];
    const float* fc1b  = (const float*)d_in[11];
    const float* fc2w  = (const float*)d_in[12];
    const float* fc2b  = (const float*)d_in[13];
    const int*   relix = (const int*)d_in[14];
    const float* mask  = (const float*)d_in[15];
    float* out = (float*)d_out;

    __nv_bfloat16 *bufA, *bufB, *bufC, *bufW;
    float *bufX, *combp;
    cudaGetSymbolAddress((void**)&bufA, g_bufA);
    cudaGetSymbolAddress((void**)&bufB, g_bufB);
    cudaGetSymbolAddress((void**)&bufC, g_bufC);
    cudaGetSymbolAddress((void**)&bufX, g_bufX);
    cudaGetSymbolAddress((void**)&bufW, g_bufW);
    cudaGetSymbolAddress((void**)&combp, g_comb);

    __nv_bfloat16* wqkv = bufW;
    __nv_bfloat16* wprj = wqkv + 196608;
    __nv_bfloat16* wfc1 = wprj + 65536;
    __nv_bfloat16* wfc2 = wfc1 + 262144;

    const int LN_BLOCKS = T_TOK / 8;
    const int MT = T_TOK / 128;             // 784
    const int SH3  = 2 * STG3 * 4;          // 73728
    const int SHP  = 3 * STAGE_WORDS * 4;   // 92160

    cudaFuncSetAttribute(mgemm3_kernel<0>, cudaFuncAttributeMaxDynamicSharedMemorySize, SH3);
    cudaFuncSetAttribute(mgemm3_kernel<1>, cudaFuncAttributeMaxDynamicSharedMemorySize, SH3);
    cudaFuncSetAttribute(mgemm3_kernel<2>, cudaFuncAttributeMaxDynamicSharedMemorySize, SH3);
    cudaFuncSetAttribute(proj_kernel, cudaFuncAttributeMaxDynamicSharedMemorySize, SHP);

    // 0) weight conversion + combined bias table
    convw_kernel<<<(786432 + 255) / 256, 256>>>(qkvw, projw, fc1w, fc2w, bufW);
    comb_kernel<<<NWIN * HEADS, 256>>>(rpb, relix, mask, combp);

    // 1) LN1 + shift + window partition -> bufB (bf16)
    ln_kernel<<<LN_BLOCKS, 256>>>(x, n1w, n1b, bufB);

    // 2) qkv GEMM -> bufA [T,768] (bf16)
    mgemm3_kernel<0><<<dim3(768 / 128, MT), 256, SH3>>>(
        bufB, wqkv, qkvb, nullptr, bufA, 768, DIM);

    // 3) MMA attention -> bufB (bf16, window order)
    attn_kernel<<<(T_TOK / NTOK) * HEADS, 128>>>(bufA, combp, bufB);

    // 4) proj + scatter + residual + fused LN2 -> bufX (fp32), bufC (bf16)
    proj_kernel<<<dim3(1, MT), 512, SHP>>>(
        bufB, wprj, projb, x, bufX, bufC, n2w, n2b);

    // 5) fc1 + GELU -> bufA [T,1024] (bf16)
    mgemm3_kernel<1><<<dim3(HIDDEN / 128, MT), 256, SH3>>>(
        bufC, wfc1, fc1b, nullptr, bufA, HIDDEN, DIM);

    // 6) fc2 + residual -> d_out (fp32)
    mgemm3_kernel<2><<<dim3(DIM / 128, MT), 256, SH3>>>(
        bufA, wfc2, fc2b, bufX, out, DIM, HIDDEN);
}